// round 7
// baseline (speedup 1.0000x reference)
#include <cuda_runtime.h>
#include <cuda_fp16.h>
#include <math.h>
#include <stdint.h>

// ---------------- problem constants ----------------
#define BB 4
#define TT 4096
#define DD 1024
#define KK 128
#define HH 8
#define KER 4
#define MM 4096          // mlp hidden
#define C2K 256          // 2*K
#define NT (BB*TT)       // 16384 rows

// ---------------- scratch (static device, no allocs) ----------------
__device__ __half g_xn_h[(size_t)NT*DD];     // LN1 out fp16
__device__ __half g_y_h[(size_t)NT*DD];      // LN2 out fp16
__device__ __half g_h1_h[(size_t)NT*MM];     // mlp mid fp16
__device__ __half g_eig_h[(size_t)NT*C2K];   // fp16 copy of eig
__device__ __half g_pe_h[(size_t)NT*C2K];    // fp16 prev_eig
__device__ __half g_sig_h[(size_t)NT*DD];    // sigmoid gate fp16
__device__ float  g_beta0[(size_t)NT*C2K];
__device__ float  g_pm[(size_t)NT*C2K];
__device__ float  g_cR[(size_t)BB*KK*TT];
__device__ float  g_cI[(size_t)BB*KK*TT];
__device__ float  g_x1[(size_t)NT*DD];
// fp16 weights, packed: [in_proj(256) ; gate(1024)] x K=1024 first (fused GEMM)
#define W_IPGATE  0
#define W_MEMPROJ (W_IPGATE + 1280*DD)
#define W_OUTPROJ (W_MEMPROJ + C2K*C2K)
#define W_MLP1    (W_OUTPROJ + DD*C2K)
#define W_MLP2    (W_MLP1 + (size_t)MM*DD)
#define W_TOTAL   (W_MLP2 + (size_t)DD*MM)
__device__ __half g_wh[W_TOTAL];

__device__ __forceinline__ float sigmf(float x) { return 1.f / (1.f + __expf(-x)); }
__device__ __forceinline__ uint32_t smem_u32(const void* p) {
    uint32_t a;
    asm("{ .reg .u64 t; cvta.to.shared.u64 t, %1; cvt.u32.u64 %0, t; }" : "=r"(a) : "l"(p));
    return a;
}
__device__ __forceinline__ void cp16(uint32_t s, const void* g) {
    asm volatile("cp.async.cg.shared.global [%0], [%1], 16;" :: "r"(s), "l"(g));
}
__device__ __forceinline__ uint32_t h2u(__half2 h) { return *(uint32_t*)&h; }
__device__ __forceinline__ void ldsm_x4(uint32_t& r0, uint32_t& r1, uint32_t& r2, uint32_t& r3,
                                        uint32_t addr) {
    asm volatile("ldmatrix.sync.aligned.m8n8.x4.shared.b16 {%0,%1,%2,%3}, [%4];"
                 : "=r"(r0), "=r"(r1), "=r"(r2), "=r"(r3) : "r"(addr));
}

// ============================ batched fp32 -> fp16 ============================
struct CvtArgs {
    const float* src[7];
    __half* dst[7];
    int n8[7];
};
__global__ void cvt_all_kernel(CvtArgs a)
{
    const int seg = blockIdx.y;
    const int i = blockIdx.x * blockDim.x + threadIdx.x;
    if (i < a.n8[seg]) {
        const float4* s4 = (const float4*)a.src[seg] + 2 * (size_t)i;
        float4 p = s4[0], q = s4[1];
        uint4 o = {h2u(__floats2half2_rn(p.x, p.y)), h2u(__floats2half2_rn(p.z, p.w)),
                   h2u(__floats2half2_rn(q.x, q.y)), h2u(__floats2half2_rn(q.z, q.w))};
        ((uint4*)a.dst[seg])[i] = o;
    }
}

// ============================ LayerNorm -> fp16 out ============================
__global__ void ten_ln_kernel(const float* __restrict__ x,
                              const float* __restrict__ gw,
                              const float* __restrict__ bw,
                              __half* __restrict__ yh)
{
    const int row = blockIdx.x;
    const int tid = threadIdx.x;
    const float4* xr = (const float4*)(x + (size_t)row * DD);
    float4 v = xr[tid];
    float s = v.x + v.y + v.z + v.w;
    float q = v.x*v.x + v.y*v.y + v.z*v.z + v.w*v.w;
    #pragma unroll
    for (int o = 16; o > 0; o >>= 1) {
        s += __shfl_xor_sync(0xffffffffu, s, o);
        q += __shfl_xor_sync(0xffffffffu, q, o);
    }
    __shared__ float ss[8], sq[8];
    const int w = tid >> 5, l = tid & 31;
    if (l == 0) { ss[w] = s; sq[w] = q; }
    __syncthreads();
    float st = 0.f, qt = 0.f;
    #pragma unroll
    for (int i = 0; i < 8; i++) { st += ss[i]; qt += sq[i]; }
    const float mean = st * (1.f / DD);
    const float var  = qt * (1.f / DD) - mean * mean;
    const float rstd = rsqrtf(var + 1e-5f);
    float4 g4 = ((const float4*)gw)[tid];
    float4 b4 = ((const float4*)bw)[tid];
    float ox = (v.x - mean) * rstd * g4.x + b4.x;
    float oy = (v.y - mean) * rstd * g4.y + b4.y;
    float oz = (v.z - mean) * rstd * g4.z + b4.z;
    float ow = (v.w - mean) * rstd * g4.w + b4.w;
    uint2 ov = {h2u(__floats2half2_rn(ox, oy)), h2u(__floats2half2_rn(oz, ow))};
    ((uint2*)(yh + (size_t)row * DD))[tid] = ov;
}

// ============================ fp16 mma.sync GEMM ============================
// C[M,N] = A[M,K] @ B[N,K]^T ; block 128x128, BK=64 halves, 3-stage cp.async,
// 8 warps (2x4), warp tile 64x32 (4x4 m16n8k16), ldmatrix loads, 2 CTAs/SM.
enum { EPI_NONE = 0, EPI_GATE = 2, EPI_SILU_H = 3, EPI_BIAS_RES = 4, EPI_IPGATE = 5 };

#define ASTR 36                    // b32 per SMEM row (32 data + 4 pad)
#define ROWB (ASTR*4)              // 144 bytes per row
#define A_B32 (128*ASTR)
#define B_B32 (128*ASTR)
#define ST_B32 (A_B32 + B_B32)     // 9216 b32
#define GEMM_SMEM (3*ST_B32*4)     // 110592 B

template<int EPI>
__global__ void __launch_bounds__(256, 2)
mma_gemm(const __half* __restrict__ A, const __half* __restrict__ B, void* Cv,
         int M, int N, int K,
         const float* __restrict__ aux0, const void* __restrict__ aux1,
         const float* __restrict__ aux2, void* Cv2)
{
    extern __shared__ uint32_t smu[];
    const uint32_t sm_base = smem_u32(smu);
    const int tid = threadIdx.x;
    const int lane = tid & 31, wid = tid >> 5;
    const int wm = wid >> 2, wn = wid & 3;          // 2 x 4 warp grid
    const int m0 = blockIdx.y * 128, n0 = blockIdx.x * 128;
    const int nchunk = K >> 6;
    const int g = lane >> 2, t = lane & 3;

    const __half* Ag = A + (size_t)m0 * K;
    const __half* Bg = B + (size_t)n0 * K;

    auto load_stage = [&](int s, int c) {
        const uint32_t sb = sm_base + (uint32_t)(s * ST_B32) * 4;
        const __half* ac = Ag + (size_t)c * 64;
        #pragma unroll
        for (int j = 0; j < 4; j++) {
            int idx = tid + j * 256; int r = idx >> 3; int u = idx & 7;
            cp16(sb + (uint32_t)(r * ASTR + u * 4) * 4, ac + (size_t)r * K + u * 8);
        }
        const __half* bc = Bg + (size_t)c * 64;
        #pragma unroll
        for (int j = 0; j < 4; j++) {
            int idx = tid + j * 256; int r = idx >> 3; int u = idx & 7;
            cp16(sb + (uint32_t)(A_B32 + r * ASTR + u * 4) * 4, bc + (size_t)r * K + u * 8);
        }
        asm volatile("cp.async.commit_group;");
    };

    float acc[4][4][4];
    #pragma unroll
    for (int mi = 0; mi < 4; mi++)
        #pragma unroll
        for (int ni = 0; ni < 4; ni++)
            #pragma unroll
            for (int q = 0; q < 4; q++) acc[mi][ni][q] = 0.f;

    load_stage(0, 0);
    if (1 < nchunk) load_stage(1, 1);

    const uint32_t aOff = (uint32_t)(wm * 64 + (lane & 15)) * ROWB + (uint32_t)(lane >> 4) * 16;
    const uint32_t bOff = (uint32_t)A_B32 * 4 +
        (uint32_t)(wn * 32 + (lane & 7) + ((lane >> 4) & 1) * 8) * ROWB +
        (uint32_t)((lane >> 3) & 1) * 16;

    int stage = 0;
    for (int i = 0; i < nchunk; i++) {
        if (i == nchunk - 1) asm volatile("cp.async.wait_group 0;" ::: "memory");
        else                 asm volatile("cp.async.wait_group 1;" ::: "memory");
        __syncthreads();
        if (i + 2 < nchunk) {
            int ns = stage + 2; if (ns >= 3) ns -= 3;
            load_stage(ns, i + 2);
        }
        const uint32_t stBase = sm_base + (uint32_t)(stage * ST_B32) * 4;
        #pragma unroll
        for (int ks = 0; ks < 4; ks++) {
            const uint32_t kb = (uint32_t)ks * 32;
            uint32_t af[4][4], bf[4][2];
            #pragma unroll
            for (int mi = 0; mi < 4; mi++)
                ldsm_x4(af[mi][0], af[mi][1], af[mi][2], af[mi][3],
                        stBase + aOff + (uint32_t)mi * (16 * ROWB) + kb);
            #pragma unroll
            for (int np = 0; np < 2; np++)
                ldsm_x4(bf[2*np][0], bf[2*np][1], bf[2*np+1][0], bf[2*np+1][1],
                        stBase + bOff + (uint32_t)np * (16 * ROWB) + kb);
            #pragma unroll
            for (int mi = 0; mi < 4; mi++)
                #pragma unroll
                for (int ni = 0; ni < 4; ni++)
                    asm volatile(
                        "mma.sync.aligned.m16n8k16.row.col.f32.f16.f16.f32 "
                        "{%0,%1,%2,%3}, {%4,%5,%6,%7}, {%8,%9}, {%0,%1,%2,%3};"
                        : "+f"(acc[mi][ni][0]), "+f"(acc[mi][ni][1]),
                          "+f"(acc[mi][ni][2]), "+f"(acc[mi][ni][3])
                        : "r"(af[mi][0]), "r"(af[mi][1]), "r"(af[mi][2]), "r"(af[mi][3]),
                          "r"(bf[ni][0]), "r"(bf[ni][1]));
        }
        if (++stage == 3) stage = 0;
    }

    // -------- epilogue --------
    float* Cf = (float*)Cv;
    __half* Ch = (__half*)Cv;
    const __half* sgh = (const __half*)aux1;   // EPI_GATE: fp16 sigmoid gate
    #pragma unroll
    for (int mi = 0; mi < 4; mi++) {
        const int rbase = m0 + wm * 64 + mi * 16 + g;
        #pragma unroll
        for (int ni = 0; ni < 4; ni++) {
            const int cc = n0 + wn * 32 + ni * 8 + t * 2;
            #pragma unroll
            for (int half_ = 0; half_ < 2; half_++) {
                const int r = rbase + half_ * 8;
                float v0 = acc[mi][ni][half_ * 2 + 0];
                float v1 = acc[mi][ni][half_ * 2 + 1];
                const size_t off = (size_t)r * N + cc;
                if (EPI == EPI_NONE) {
                    float2 o = {v0, v1};
                    *(float2*)(Cf + off) = o;
                } else if (EPI == EPI_IPGATE) {
                    // cols [0,256): beta0 fp32 (stride 256); cols [256,1280): sigmoid fp16 (stride 1024)
                    if (cc < 256) {
                        float2 o = {v0, v1};
                        *(float2*)(Cf + (size_t)r * 256 + cc) = o;
                    } else {
                        const int c2 = cc - 256;
                        float2 gb = *(const float2*)(aux0 + c2);
                        __half2 o = __floats2half2_rn(sigmf(v0 + gb.x), sigmf(v1 + gb.y));
                        *(uint32_t*)((__half*)Cv2 + (size_t)r * 1024 + c2) = h2u(o);
                    }
                } else if (EPI == EPI_GATE) {
                    uint32_t su = *(const uint32_t*)(sgh + off);
                    float2 sg = __half22float2(*(__half2*)&su);
                    float2 xr = *(const float2*)(aux2 + off);
                    float2 o = {xr.x + sg.x * v0, xr.y + sg.y * v1};
                    *(float2*)(Cf + off) = o;
                } else if (EPI == EPI_SILU_H) {
                    float2 bb = *(const float2*)(aux0 + cc);
                    float t0 = v0 + bb.x, t1 = v1 + bb.y;
                    __half2 o = __floats2half2_rn(t0 * sigmf(t0), t1 * sigmf(t1));
                    *(uint32_t*)(Ch + off) = h2u(o);
                } else if (EPI == EPI_BIAS_RES) {
                    float2 bb = *(const float2*)(aux0 + cc);
                    float2 xr = *(const float2*)(aux2 + off);
                    float2 o = {xr.x + v0 + bb.x, xr.y + v1 + bb.y};
                    *(float2*)(Cf + off) = o;
                }
            }
        }
    }
}

// ---------- fused: depthwise conv(4) + bias + SiLU + mem inject + complex scan ----------
// one block per (b,k); conv computed on the fly from beta0/pm columns.
__global__ void __launch_bounds__(256)
ten_convscan_kernel(const float* __restrict__ beta0,
                    const float* __restrict__ pm,
                    const float* __restrict__ conv_w,
                    const float* __restrict__ conv_b,
                    const float* __restrict__ mem_gate,
                    const float* __restrict__ log_decay,
                    const float* __restrict__ freq,
                    float* __restrict__ cR, float* __restrict__ cI)
{
    const int bk = blockIdx.x;
    const int b = bk >> 7, k = bk & (KK - 1);
    const int tid = threadIdx.x;
    const int base_t = tid * 16;
    const float mg = 1.f / (1.f + expf(-mem_gate[0]));

    // conv params: real channel k, imag channel k+KK
    const float w0r = conv_w[k*4+0], w1r = conv_w[k*4+1], w2r = conv_w[k*4+2], w3r = conv_w[k*4+3];
    const float cbr = conv_b[k];
    const int ci = k + KK;
    const float w0i = conv_w[ci*4+0], w1i = conv_w[ci*4+1], w2i = conv_w[ci*4+2], w3i = conv_w[ci*4+3];
    const float cbi = conv_b[ci];

    float xr[16], xi[16];
    {
        float wr[19], wi_[19];
        #pragma unroll
        for (int j = 0; j < 19; j++) {
            const int t = base_t - 3 + j;
            if (t >= 0) {
                const size_t o = ((size_t)(b * TT + t)) * C2K;
                wr[j]  = beta0[o + k];
                wi_[j] = beta0[o + ci];
            } else { wr[j] = 0.f; wi_[j] = 0.f; }
        }
        #pragma unroll
        for (int j = 0; j < 16; j++) {
            const size_t op = ((size_t)(b * TT + base_t + j)) * C2K;
            float vr = wr[j]*w0r + wr[j+1]*w1r + wr[j+2]*w2r + wr[j+3]*w3r + cbr;
            vr = vr * (1.f / (1.f + __expf(-vr)));
            xr[j] = vr + mg * pm[op + k];
            float vi = wi_[j]*w0i + wi_[j+1]*w1i + wi_[j+2]*w2i + wi_[j+3]*w3i + cbi;
            vi = vi * (1.f / (1.f + __expf(-vi)));
            xi[j] = vi + mg * pm[op + ci];
        }
    }

    // ---- scan: c[t] = lambda*c[t-1] + x[t] ----
    const float mag = 1.f / (1.f + expf(-log_decay[k]));
    float snf, csf;
    sincosf(freq[k], &snf, &csf);
    const float lr = mag * csf, li = mag * snf;

    float cr = 0.f, ci_ = 0.f;
    #pragma unroll
    for (int j = 0; j < 16; j++) {
        float nr = fmaf(lr, cr, fmaf(-li, ci_, xr[j]));
        float ni = fmaf(lr, ci_, fmaf( li, cr, xi[j]));
        cr = nr; ci_ = ni;
        xr[j] = cr; xi[j] = ci_;
    }

    float fr = lr, fi = li;
    #pragma unroll
    for (int s = 0; s < 4; s++) {
        float nr = fr * fr - fi * fi;
        float ni = 2.f * fr * fi;
        fr = nr; fi = ni;
    }

    __shared__ float sgr[256], sgi[256], sor[256], soi[256];
    sgr[tid] = fr; sgi[tid] = fi; sor[tid] = cr; soi[tid] = ci_;
    __syncthreads();
    for (int d = 1; d < 256; d <<= 1) {
        float ngr = 0.f, ngi = 0.f, nor_ = 0.f, noi_ = 0.f;
        if (tid >= d) {
            const float pgr = sgr[tid - d], pgi = sgi[tid - d];
            const float por = sor[tid - d], poi = soi[tid - d];
            const float gr = sgr[tid], gi = sgi[tid];
            const float orr = sor[tid], oii = soi[tid];
            ngr  = gr * pgr - gi * pgi;
            ngi  = gr * pgi + gi * pgr;
            nor_ = gr * por - gi * poi + orr;
            noi_ = gr * poi + gi * por + oii;
        }
        __syncthreads();
        if (tid >= d) { sgr[tid] = ngr; sgi[tid] = ngi; sor[tid] = nor_; soi[tid] = noi_; }
        __syncthreads();
    }
    const float pr = (tid > 0) ? sor[tid - 1] : 0.f;
    const float pi = (tid > 0) ? soi[tid - 1] : 0.f;

    float lpr = lr, lpi = li;
    #pragma unroll
    for (int j = 0; j < 16; j++) {
        xr[j] = fmaf(lpr, pr, fmaf(-lpi, pi, xr[j]));
        xi[j] = fmaf(lpr, pi, fmaf( lpi, pr, xi[j]));
        float nr = lpr * lr - lpi * li;
        float ni = lpr * li + lpi * lr;
        lpr = nr; lpi = ni;
    }
    const size_t base = (size_t)bk * TT + base_t;
    #pragma unroll
    for (int v = 0; v < 4; v++) {
        float4 a = {xr[v*4+0], xr[v*4+1], xr[v*4+2], xr[v*4+3]};
        *(float4*)(cR + base + v * 4) = a;
        float4 c = {xi[v*4+0], xi[v*4+1], xi[v*4+2], xi[v*4+3]};
        *(float4*)(cI + base + v * 4) = c;
    }
}

// ---------------- coupling + transpose -> eig fp32 (output) + fp16 copy -----
__global__ void __launch_bounds__(256)
ten_coupling_kernel(const float* __restrict__ cR, const float* __restrict__ cI,
                    const float* __restrict__ coupling,
                    float* __restrict__ eig, __half* __restrict__ eig_h)
{
    const int b = blockIdx.z, h = blockIdx.y;
    const int t0 = blockIdx.x * 256;
    const int tid = threadIdx.x;
    __shared__ float sr[16][256];
    __shared__ float si[16][256];
    __shared__ float w[16][16];
    w[tid >> 4][tid & 15] = coupling[h * 256 + tid];
    #pragma unroll
    for (int kk = 0; kk < 16; kk++) {
        const size_t src = ((size_t)(b * KK + h * 16 + kk)) * TT + t0 + tid;
        sr[kk][tid] = cR[src];
        si[kk][tid] = cI[src];
    }
    __syncthreads();
    float orr[16], oii[16];
    #pragma unroll
    for (int j = 0; j < 16; j++) { orr[j] = 0.f; oii[j] = 0.f; }
    #pragma unroll
    for (int kk = 0; kk < 16; kk++) {
        const float vr = sr[kk][tid];
        const float vi = si[kk][tid];
        #pragma unroll
        for (int j = 0; j < 16; j++) {
            orr[j] = fmaf(w[j][kk], vr, orr[j]);
            oii[j] = fmaf(w[j][kk], vi, oii[j]);
        }
    }
    const size_t dst = ((size_t)(b * TT + t0 + tid)) * C2K + h * 16;
    #pragma unroll
    for (int j = 0; j < 16; j += 4) {
        float4 v = {orr[j], orr[j+1], orr[j+2], orr[j+3]};
        *(float4*)(eig + dst + j) = v;
        float4 u = {oii[j], oii[j+1], oii[j+2], oii[j+3]};
        *(float4*)(eig + dst + KK + j) = u;
        uint2 vv = {h2u(__floats2half2_rn(orr[j], orr[j+1])),
                    h2u(__floats2half2_rn(orr[j+2], orr[j+3]))};
        *(uint2*)(eig_h + dst + j) = vv;
        uint2 uu = {h2u(__floats2half2_rn(oii[j], oii[j+1])),
                    h2u(__floats2half2_rn(oii[j+2], oii[j+3]))};
        *(uint2*)(eig_h + dst + KK + j) = uu;
    }
}

// ---------------- launch -----------------------------------------------------
extern "C" void kernel_launch(void* const* d_in, const int* in_sizes, int n_in,
                              void* d_out, int out_size)
{
    const float* x          = (const float*)d_in[0];
    const float* prev_eig   = (const float*)d_in[1];
    const float* in_proj_w  = (const float*)d_in[2];
    const float* conv_w     = (const float*)d_in[3];
    const float* conv_b     = (const float*)d_in[4];
    const float* mem_gate   = (const float*)d_in[5];
    const float* mem_proj_w = (const float*)d_in[6];
    const float* log_decay  = (const float*)d_in[7];
    const float* frequency  = (const float*)d_in[8];
    const float* coupling   = (const float*)d_in[9];
    const float* out_proj_w = (const float*)d_in[10];
    const float* gate_w     = (const float*)d_in[11];
    const float* gate_b     = (const float*)d_in[12];
    const float* mlp_w1     = (const float*)d_in[13];
    const float* mlp_b1     = (const float*)d_in[14];
    const float* mlp_w2     = (const float*)d_in[15];
    const float* mlp_b2     = (const float*)d_in[16];
    const float* n1_g       = (const float*)d_in[17];
    const float* n1_b       = (const float*)d_in[18];
    const float* n2_g       = (const float*)d_in[19];
    const float* n2_b       = (const float*)d_in[20];

    float* out_x2  = (float*)d_out;
    float* out_eig = out_x2 + (size_t)NT * DD;

    __half *xn_h, *y_h, *h1_h, *eig_h, *pe_h, *sig_h, *wh;
    float *beta0, *pm, *cRp, *cIp, *x1;
    cudaGetSymbolAddress((void**)&xn_h,  g_xn_h);
    cudaGetSymbolAddress((void**)&y_h,   g_y_h);
    cudaGetSymbolAddress((void**)&h1_h,  g_h1_h);
    cudaGetSymbolAddress((void**)&eig_h, g_eig_h);
    cudaGetSymbolAddress((void**)&pe_h,  g_pe_h);
    cudaGetSymbolAddress((void**)&sig_h, g_sig_h);
    cudaGetSymbolAddress((void**)&wh,    g_wh);
    cudaGetSymbolAddress((void**)&beta0, g_beta0);
    cudaGetSymbolAddress((void**)&pm,    g_pm);
    cudaGetSymbolAddress((void**)&cRp,   g_cR);
    cudaGetSymbolAddress((void**)&cIp,   g_cI);
    cudaGetSymbolAddress((void**)&x1,    g_x1);

    cudaFuncSetAttribute(mma_gemm<EPI_NONE>,     cudaFuncAttributeMaxDynamicSharedMemorySize, GEMM_SMEM);
    cudaFuncSetAttribute(mma_gemm<EPI_IPGATE>,   cudaFuncAttributeMaxDynamicSharedMemorySize, GEMM_SMEM);
    cudaFuncSetAttribute(mma_gemm<EPI_GATE>,     cudaFuncAttributeMaxDynamicSharedMemorySize, GEMM_SMEM);
    cudaFuncSetAttribute(mma_gemm<EPI_SILU_H>,   cudaFuncAttributeMaxDynamicSharedMemorySize, GEMM_SMEM);
    cudaFuncSetAttribute(mma_gemm<EPI_BIAS_RES>, cudaFuncAttributeMaxDynamicSharedMemorySize, GEMM_SMEM);

    // batched weight/activation conversion (7 segments, one launch)
    // in_proj (256xK) and gate (1024xK) packed adjacently -> fused GEMM weight [1280,1024]
    CvtArgs ca;
    ca.src[0] = in_proj_w;  ca.dst[0] = wh + W_IPGATE;           ca.n8[0] = (int)((size_t)C2K * DD / 8);
    ca.src[1] = gate_w;     ca.dst[1] = wh + W_IPGATE + C2K*DD;  ca.n8[1] = (int)((size_t)DD * DD / 8);
    ca.src[2] = mem_proj_w; ca.dst[2] = wh + W_MEMPROJ;          ca.n8[2] = (int)((size_t)C2K * C2K / 8);
    ca.src[3] = out_proj_w; ca.dst[3] = wh + W_OUTPROJ;          ca.n8[3] = (int)((size_t)DD * C2K / 8);
    ca.src[4] = mlp_w1;     ca.dst[4] = wh + W_MLP1;             ca.n8[4] = (int)((size_t)MM * DD / 8);
    ca.src[5] = mlp_w2;     ca.dst[5] = wh + W_MLP2;             ca.n8[5] = (int)((size_t)DD * MM / 8);
    ca.src[6] = prev_eig;   ca.dst[6] = pe_h;                    ca.n8[6] = (int)((size_t)NT * C2K / 8);
    cvt_all_kernel<<<dim3(2048, 7), 256>>>(ca);

    // 1) pm = prev_eig @ mem_proj_w^T  [16384,256] (independent of LN1)
    mma_gemm<EPI_NONE><<<dim3(C2K/128, NT/128), 256, GEMM_SMEM>>>(
        pe_h, wh + W_MEMPROJ, pm, NT, C2K, C2K, nullptr, nullptr, nullptr, nullptr);

    // 2) LN1 -> fp16
    ten_ln_kernel<<<NT, 256>>>(x, n1_g, n1_b, xn_h);

    // 3) fused in_proj + gate: cols 0-255 -> beta0 fp32, cols 256-1279 -> sigmoid fp16
    mma_gemm<EPI_IPGATE><<<dim3(1280/128, NT/128), 256, GEMM_SMEM>>>(
        xn_h, wh + W_IPGATE, beta0, NT, 1280, DD, gate_b, nullptr, nullptr, sig_h);

    // 4) fused conv + mem inject + scan
    ten_convscan_kernel<<<BB * KK, 256>>>(
        beta0, pm, conv_w, conv_b, mem_gate, log_decay, frequency, cRp, cIp);

    // 5) coupling -> eig fp32 (output) + fp16 copy
    ten_coupling_kernel<<<dim3(TT/256, HH, BB), 256>>>(cRp, cIp, coupling, out_eig, eig_h);

    // 6) x1 = x + sig * (eig @ out_proj^T)
    mma_gemm<EPI_GATE><<<dim3(DD/128, NT/128), 256, GEMM_SMEM>>>(
        eig_h, wh + W_OUTPROJ, x1, NT, DD, C2K, nullptr, sig_h, x, nullptr);

    // 7) LN2 -> fp16
    ten_ln_kernel<<<NT, 256>>>(x1, n2_g, n2_b, y_h);

    // 8) h1 = silu(y @ w1^T + b1) fp16  [16384,4096]
    mma_gemm<EPI_SILU_H><<<dim3(MM/128, NT/128), 256, GEMM_SMEM>>>(
        y_h, wh + W_MLP1, h1_h, NT, MM, DD, mlp_b1, nullptr, nullptr, nullptr);

    // 9) x2 = x1 + h1 @ w2^T + b2  [16384,1024]
    mma_gemm<EPI_BIAS_RES><<<dim3(DD/128, NT/128), 256, GEMM_SMEM>>>(
        h1_h, wh + W_MLP2, out_x2, NT, DD, MM, mlp_b2, nullptr, x1, nullptr);
}

// round 8
// speedup vs baseline: 1.0042x; 1.0042x over previous
#include <cuda_runtime.h>
#include <cuda_fp16.h>
#include <math.h>
#include <stdint.h>

// ---------------- problem constants ----------------
#define BB 4
#define TT 4096
#define DD 1024
#define KK 128
#define HH 8
#define KER 4
#define MM 4096          // mlp hidden
#define C2K 256          // 2*K
#define NT (BB*TT)       // 16384 rows

// ---------------- scratch (static device, no allocs) ----------------
__device__ __half g_xn_h[(size_t)NT*DD];     // LN1 out fp16
__device__ __half g_y_h[(size_t)NT*DD];      // LN2 out fp16
__device__ __half g_h1_h[(size_t)NT*MM];     // mlp mid fp16
__device__ __half g_eig_h[(size_t)NT*C2K];   // fp16 copy of eig
__device__ __half g_pe_h[(size_t)NT*C2K];    // fp16 prev_eig
__device__ __half g_sig_h[(size_t)NT*DD];    // sigmoid gate fp16
__device__ float  g_beta0[(size_t)NT*C2K];
__device__ float  g_pm[(size_t)NT*C2K];
__device__ float  g_cR[(size_t)BB*KK*TT];
__device__ float  g_cI[(size_t)BB*KK*TT];
__device__ float  g_x1[(size_t)NT*DD];
// fp16 weights, packed: [in_proj(256) ; gate(1024)] x K=1024 first (fused GEMM)
#define W_IPGATE  0
#define W_MEMPROJ (W_IPGATE + 1280*DD)
#define W_OUTPROJ (W_MEMPROJ + C2K*C2K)
#define W_MLP1    (W_OUTPROJ + DD*C2K)
#define W_MLP2    (W_MLP1 + (size_t)MM*DD)
#define W_TOTAL   (W_MLP2 + (size_t)DD*MM)
__device__ __half g_wh[W_TOTAL];

__device__ __forceinline__ float sigmf(float x) { return 1.f / (1.f + __expf(-x)); }
__device__ __forceinline__ uint32_t smem_u32(const void* p) {
    uint32_t a;
    asm("{ .reg .u64 t; cvta.to.shared.u64 t, %1; cvt.u32.u64 %0, t; }" : "=r"(a) : "l"(p));
    return a;
}
__device__ __forceinline__ void cp16(uint32_t s, const void* g) {
    asm volatile("cp.async.cg.shared.global [%0], [%1], 16;" :: "r"(s), "l"(g));
}
__device__ __forceinline__ uint32_t h2u(__half2 h) { return *(uint32_t*)&h; }
__device__ __forceinline__ void ldsm_x4(uint32_t& r0, uint32_t& r1, uint32_t& r2, uint32_t& r3,
                                        uint32_t addr) {
    asm volatile("ldmatrix.sync.aligned.m8n8.x4.shared.b16 {%0,%1,%2,%3}, [%4];"
                 : "=r"(r0), "=r"(r1), "=r"(r2), "=r"(r3) : "r"(addr));
}

// ============================ batched fp32 -> fp16 ============================
struct CvtArgs {
    const float* src[7];
    __half* dst[7];
    int n8[7];
};
__global__ void cvt_all_kernel(CvtArgs a)
{
    const int seg = blockIdx.y;
    const int i = blockIdx.x * blockDim.x + threadIdx.x;
    if (i < a.n8[seg]) {
        const float4* s4 = (const float4*)a.src[seg] + 2 * (size_t)i;
        float4 p = s4[0], q = s4[1];
        uint4 o = {h2u(__floats2half2_rn(p.x, p.y)), h2u(__floats2half2_rn(p.z, p.w)),
                   h2u(__floats2half2_rn(q.x, q.y)), h2u(__floats2half2_rn(q.z, q.w))};
        ((uint4*)a.dst[seg])[i] = o;
    }
}

// ============================ LayerNorm -> fp16 out ============================
__global__ void ten_ln_kernel(const float* __restrict__ x,
                              const float* __restrict__ gw,
                              const float* __restrict__ bw,
                              __half* __restrict__ yh)
{
    const int row = blockIdx.x;
    const int tid = threadIdx.x;
    const float4* xr = (const float4*)(x + (size_t)row * DD);
    float4 v = xr[tid];
    float s = v.x + v.y + v.z + v.w;
    float q = v.x*v.x + v.y*v.y + v.z*v.z + v.w*v.w;
    #pragma unroll
    for (int o = 16; o > 0; o >>= 1) {
        s += __shfl_xor_sync(0xffffffffu, s, o);
        q += __shfl_xor_sync(0xffffffffu, q, o);
    }
    __shared__ float ss[8], sq[8];
    const int w = tid >> 5, l = tid & 31;
    if (l == 0) { ss[w] = s; sq[w] = q; }
    __syncthreads();
    float st = 0.f, qt = 0.f;
    #pragma unroll
    for (int i = 0; i < 8; i++) { st += ss[i]; qt += sq[i]; }
    const float mean = st * (1.f / DD);
    const float var  = qt * (1.f / DD) - mean * mean;
    const float rstd = rsqrtf(var + 1e-5f);
    float4 g4 = ((const float4*)gw)[tid];
    float4 b4 = ((const float4*)bw)[tid];
    float ox = (v.x - mean) * rstd * g4.x + b4.x;
    float oy = (v.y - mean) * rstd * g4.y + b4.y;
    float oz = (v.z - mean) * rstd * g4.z + b4.z;
    float ow = (v.w - mean) * rstd * g4.w + b4.w;
    uint2 ov = {h2u(__floats2half2_rn(ox, oy)), h2u(__floats2half2_rn(oz, ow))};
    ((uint2*)(yh + (size_t)row * DD))[tid] = ov;
}

// ============================ fp16 mma.sync GEMM ============================
// C[M,N] = A[M,K] @ B[N,K]^T ; block 128x128, BK=64 halves, 3-stage cp.async,
// 8 warps (2x4), warp tile 64x32, ping-pong register fragments, 2 CTAs/SM.
enum { EPI_NONE = 0, EPI_GATE = 2, EPI_SILU_H = 3, EPI_BIAS_RES = 4, EPI_IPGATE = 5 };

#define ASTR 36                    // b32 per SMEM row (32 data + 4 pad)
#define ROWB (ASTR*4)              // 144 bytes per row
#define A_B32 (128*ASTR)
#define B_B32 (128*ASTR)
#define ST_B32 (A_B32 + B_B32)     // 9216 b32
#define GEMM_SMEM (3*ST_B32*4)     // 110592 B

template<int EPI>
__global__ void __launch_bounds__(256, 2)
mma_gemm(const __half* __restrict__ A, const __half* __restrict__ B, void* Cv,
         int M, int N, int K,
         const float* __restrict__ aux0, const void* __restrict__ aux1,
         const float* __restrict__ aux2, void* Cv2)
{
    extern __shared__ uint32_t smu[];
    const uint32_t sm_base = smem_u32(smu);
    const int tid = threadIdx.x;
    const int lane = tid & 31, wid = tid >> 5;
    const int wm = wid >> 2, wn = wid & 3;          // 2 x 4 warp grid
    const int m0 = blockIdx.y * 128, n0 = blockIdx.x * 128;
    const int nchunk = K >> 6;
    const int g = lane >> 2, t = lane & 3;

    const __half* Ag = A + (size_t)m0 * K;
    const __half* Bg = B + (size_t)n0 * K;

    auto load_stage = [&](int s, int c) {
        const uint32_t sb = sm_base + (uint32_t)(s * ST_B32) * 4;
        const __half* ac = Ag + (size_t)c * 64;
        #pragma unroll
        for (int j = 0; j < 4; j++) {
            int idx = tid + j * 256; int r = idx >> 3; int u = idx & 7;
            cp16(sb + (uint32_t)(r * ASTR + u * 4) * 4, ac + (size_t)r * K + u * 8);
        }
        const __half* bc = Bg + (size_t)c * 64;
        #pragma unroll
        for (int j = 0; j < 4; j++) {
            int idx = tid + j * 256; int r = idx >> 3; int u = idx & 7;
            cp16(sb + (uint32_t)(A_B32 + r * ASTR + u * 4) * 4, bc + (size_t)r * K + u * 8);
        }
        asm volatile("cp.async.commit_group;");
    };

    float acc[4][4][4];
    #pragma unroll
    for (int mi = 0; mi < 4; mi++)
        #pragma unroll
        for (int ni = 0; ni < 4; ni++)
            #pragma unroll
            for (int q = 0; q < 4; q++) acc[mi][ni][q] = 0.f;

    load_stage(0, 0);
    if (1 < nchunk) load_stage(1, 1);

    const uint32_t aOff = (uint32_t)(wm * 64 + (lane & 15)) * ROWB + (uint32_t)(lane >> 4) * 16;
    const uint32_t bOff = (uint32_t)A_B32 * 4 +
        (uint32_t)(wn * 32 + (lane & 7) + ((lane >> 4) & 1) * 8) * ROWB +
        (uint32_t)((lane >> 3) & 1) * 16;

    // ping-pong fragment buffers: A at mi granularity, B at ks granularity
    uint32_t abuf[2][4], bbuf[2][8];

    int stage = 0;
    for (int i = 0; i < nchunk; i++) {
        if (i == nchunk - 1) asm volatile("cp.async.wait_group 0;" ::: "memory");
        else                 asm volatile("cp.async.wait_group 1;" ::: "memory");
        __syncthreads();
        if (i + 2 < nchunk) {
            int ns = stage + 2; if (ns >= 3) ns -= 3;
            load_stage(ns, i + 2);
        }
        const uint32_t stBase = sm_base + (uint32_t)(stage * ST_B32) * 4;

        // preload ks=0: B (2 ldsm) and A mi=0 (1 ldsm)
        ldsm_x4(bbuf[0][0], bbuf[0][1], bbuf[0][2], bbuf[0][3], stBase + bOff);
        ldsm_x4(bbuf[0][4], bbuf[0][5], bbuf[0][6], bbuf[0][7], stBase + bOff + 16 * ROWB);
        ldsm_x4(abuf[0][0], abuf[0][1], abuf[0][2], abuf[0][3], stBase + aOff);

        #pragma unroll
        for (int ks = 0; ks < 4; ks++) {
            const int cb = ks & 1;
            #pragma unroll
            for (int mi = 0; mi < 4; mi++) {
                const int ca = mi & 1;
                // prefetch next A fragment
                if (mi < 3) {
                    ldsm_x4(abuf[ca^1][0], abuf[ca^1][1], abuf[ca^1][2], abuf[ca^1][3],
                            stBase + aOff + (uint32_t)(mi + 1) * (16 * ROWB) + (uint32_t)ks * 32);
                } else if (ks < 3) {
                    ldsm_x4(abuf[ca^1][0], abuf[ca^1][1], abuf[ca^1][2], abuf[ca^1][3],
                            stBase + aOff + (uint32_t)(ks + 1) * 32);
                }
                // prefetch next B fragments once per ks
                if (mi == 0 && ks < 3) {
                    ldsm_x4(bbuf[cb^1][0], bbuf[cb^1][1], bbuf[cb^1][2], bbuf[cb^1][3],
                            stBase + bOff + (uint32_t)(ks + 1) * 32);
                    ldsm_x4(bbuf[cb^1][4], bbuf[cb^1][5], bbuf[cb^1][6], bbuf[cb^1][7],
                            stBase + bOff + 16 * ROWB + (uint32_t)(ks + 1) * 32);
                }
                #pragma unroll
                for (int ni = 0; ni < 4; ni++)
                    asm volatile(
                        "mma.sync.aligned.m16n8k16.row.col.f32.f16.f16.f32 "
                        "{%0,%1,%2,%3}, {%4,%5,%6,%7}, {%8,%9}, {%0,%1,%2,%3};"
                        : "+f"(acc[mi][ni][0]), "+f"(acc[mi][ni][1]),
                          "+f"(acc[mi][ni][2]), "+f"(acc[mi][ni][3])
                        : "r"(abuf[ca][0]), "r"(abuf[ca][1]), "r"(abuf[ca][2]), "r"(abuf[ca][3]),
                          "r"(bbuf[cb][ni*2]), "r"(bbuf[cb][ni*2+1]));
            }
        }
        if (++stage == 3) stage = 0;
    }

    // -------- epilogue --------
    float* Cf = (float*)Cv;
    __half* Ch = (__half*)Cv;
    const __half* sgh = (const __half*)aux1;   // EPI_GATE: fp16 sigmoid gate
    #pragma unroll
    for (int mi = 0; mi < 4; mi++) {
        const int rbase = m0 + wm * 64 + mi * 16 + g;
        #pragma unroll
        for (int ni = 0; ni < 4; ni++) {
            const int cc = n0 + wn * 32 + ni * 8 + t * 2;
            #pragma unroll
            for (int half_ = 0; half_ < 2; half_++) {
                const int r = rbase + half_ * 8;
                float v0 = acc[mi][ni][half_ * 2 + 0];
                float v1 = acc[mi][ni][half_ * 2 + 1];
                const size_t off = (size_t)r * N + cc;
                if (EPI == EPI_NONE) {
                    float2 o = {v0, v1};
                    *(float2*)(Cf + off) = o;
                } else if (EPI == EPI_IPGATE) {
                    // cols [0,256): beta0 fp32 (stride 256); cols [256,1280): sigmoid fp16 (stride 1024)
                    if (cc < 256) {
                        float2 o = {v0, v1};
                        *(float2*)(Cf + (size_t)r * 256 + cc) = o;
                    } else {
                        const int c2 = cc - 256;
                        float2 gb = *(const float2*)(aux0 + c2);
                        __half2 o = __floats2half2_rn(sigmf(v0 + gb.x), sigmf(v1 + gb.y));
                        *(uint32_t*)((__half*)Cv2 + (size_t)r * 1024 + c2) = h2u(o);
                    }
                } else if (EPI == EPI_GATE) {
                    uint32_t su = *(const uint32_t*)(sgh + off);
                    float2 sg = __half22float2(*(__half2*)&su);
                    float2 xr = *(const float2*)(aux2 + off);
                    float2 o = {xr.x + sg.x * v0, xr.y + sg.y * v1};
                    *(float2*)(Cf + off) = o;
                } else if (EPI == EPI_SILU_H) {
                    float2 bb = *(const float2*)(aux0 + cc);
                    float t0 = v0 + bb.x, t1 = v1 + bb.y;
                    __half2 o = __floats2half2_rn(t0 * sigmf(t0), t1 * sigmf(t1));
                    *(uint32_t*)(Ch + off) = h2u(o);
                } else if (EPI == EPI_BIAS_RES) {
                    float2 bb = *(const float2*)(aux0 + cc);
                    float2 xr = *(const float2*)(aux2 + off);
                    float2 o = {xr.x + v0 + bb.x, xr.y + v1 + bb.y};
                    *(float2*)(Cf + off) = o;
                }
            }
        }
    }
}

// ---------- fused: depthwise conv(4) + bias + SiLU + mem inject + complex scan ----------
__global__ void __launch_bounds__(256)
ten_convscan_kernel(const float* __restrict__ beta0,
                    const float* __restrict__ pm,
                    const float* __restrict__ conv_w,
                    const float* __restrict__ conv_b,
                    const float* __restrict__ mem_gate,
                    const float* __restrict__ log_decay,
                    const float* __restrict__ freq,
                    float* __restrict__ cR, float* __restrict__ cI)
{
    const int bk = blockIdx.x;
    const int b = bk >> 7, k = bk & (KK - 1);
    const int tid = threadIdx.x;
    const int base_t = tid * 16;
    const float mg = 1.f / (1.f + expf(-mem_gate[0]));

    const float w0r = conv_w[k*4+0], w1r = conv_w[k*4+1], w2r = conv_w[k*4+2], w3r = conv_w[k*4+3];
    const float cbr = conv_b[k];
    const int ci = k + KK;
    const float w0i = conv_w[ci*4+0], w1i = conv_w[ci*4+1], w2i = conv_w[ci*4+2], w3i = conv_w[ci*4+3];
    const float cbi = conv_b[ci];

    float xr[16], xi[16];
    {
        float wr[19], wi_[19];
        #pragma unroll
        for (int j = 0; j < 19; j++) {
            const int t = base_t - 3 + j;
            if (t >= 0) {
                const size_t o = ((size_t)(b * TT + t)) * C2K;
                wr[j]  = beta0[o + k];
                wi_[j] = beta0[o + ci];
            } else { wr[j] = 0.f; wi_[j] = 0.f; }
        }
        #pragma unroll
        for (int j = 0; j < 16; j++) {
            const size_t op = ((size_t)(b * TT + base_t + j)) * C2K;
            float vr = wr[j]*w0r + wr[j+1]*w1r + wr[j+2]*w2r + wr[j+3]*w3r + cbr;
            vr = vr * (1.f / (1.f + __expf(-vr)));
            xr[j] = vr + mg * pm[op + k];
            float vi = wi_[j]*w0i + wi_[j+1]*w1i + wi_[j+2]*w2i + wi_[j+3]*w3i + cbi;
            vi = vi * (1.f / (1.f + __expf(-vi)));
            xi[j] = vi + mg * pm[op + ci];
        }
    }

    const float mag = 1.f / (1.f + expf(-log_decay[k]));
    float snf, csf;
    sincosf(freq[k], &snf, &csf);
    const float lr = mag * csf, li = mag * snf;

    float cr = 0.f, ci_ = 0.f;
    #pragma unroll
    for (int j = 0; j < 16; j++) {
        float nr = fmaf(lr, cr, fmaf(-li, ci_, xr[j]));
        float ni = fmaf(lr, ci_, fmaf( li, cr, xi[j]));
        cr = nr; ci_ = ni;
        xr[j] = cr; xi[j] = ci_;
    }

    float fr = lr, fi = li;
    #pragma unroll
    for (int s = 0; s < 4; s++) {
        float nr = fr * fr - fi * fi;
        float ni = 2.f * fr * fi;
        fr = nr; fi = ni;
    }

    __shared__ float sgr[256], sgi[256], sor[256], soi[256];
    sgr[tid] = fr; sgi[tid] = fi; sor[tid] = cr; soi[tid] = ci_;
    __syncthreads();
    for (int d = 1; d < 256; d <<= 1) {
        float ngr = 0.f, ngi = 0.f, nor_ = 0.f, noi_ = 0.f;
        if (tid >= d) {
            const float pgr = sgr[tid - d], pgi = sgi[tid - d];
            const float por = sor[tid - d], poi = soi[tid - d];
            const float gr = sgr[tid], gi = sgi[tid];
            const float orr = sor[tid], oii = soi[tid];
            ngr  = gr * pgr - gi * pgi;
            ngi  = gr * pgi + gi * pgr;
            nor_ = gr * por - gi * poi + orr;
            noi_ = gr * poi + gi * por + oii;
        }
        __syncthreads();
        if (tid >= d) { sgr[tid] = ngr; sgi[tid] = ngi; sor[tid] = nor_; soi[tid] = noi_; }
        __syncthreads();
    }
    const float pr = (tid > 0) ? sor[tid - 1] : 0.f;
    const float pi = (tid > 0) ? soi[tid - 1] : 0.f;

    float lpr = lr, lpi = li;
    #pragma unroll
    for (int j = 0; j < 16; j++) {
        xr[j] = fmaf(lpr, pr, fmaf(-lpi, pi, xr[j]));
        xi[j] = fmaf(lpr, pi, fmaf( lpi, pr, xi[j]));
        float nr = lpr * lr - lpi * li;
        float ni = lpr * li + lpi * lr;
        lpr = nr; lpi = ni;
    }
    const size_t base = (size_t)bk * TT + base_t;
    #pragma unroll
    for (int v = 0; v < 4; v++) {
        float4 a = {xr[v*4+0], xr[v*4+1], xr[v*4+2], xr[v*4+3]};
        *(float4*)(cR + base + v * 4) = a;
        float4 c = {xi[v*4+0], xi[v*4+1], xi[v*4+2], xi[v*4+3]};
        *(float4*)(cI + base + v * 4) = c;
    }
}

// ---------------- coupling + transpose -> eig fp32 (output) + fp16 copy -----
__global__ void __launch_bounds__(256)
ten_coupling_kernel(const float* __restrict__ cR, const float* __restrict__ cI,
                    const float* __restrict__ coupling,
                    float* __restrict__ eig, __half* __restrict__ eig_h)
{
    const int b = blockIdx.z, h = blockIdx.y;
    const int t0 = blockIdx.x * 256;
    const int tid = threadIdx.x;
    __shared__ float sr[16][256];
    __shared__ float si[16][256];
    __shared__ float w[16][16];
    w[tid >> 4][tid & 15] = coupling[h * 256 + tid];
    #pragma unroll
    for (int kk = 0; kk < 16; kk++) {
        const size_t src = ((size_t)(b * KK + h * 16 + kk)) * TT + t0 + tid;
        sr[kk][tid] = cR[src];
        si[kk][tid] = cI[src];
    }
    __syncthreads();
    float orr[16], oii[16];
    #pragma unroll
    for (int j = 0; j < 16; j++) { orr[j] = 0.f; oii[j] = 0.f; }
    #pragma unroll
    for (int kk = 0; kk < 16; kk++) {
        const float vr = sr[kk][tid];
        const float vi = si[kk][tid];
        #pragma unroll
        for (int j = 0; j < 16; j++) {
            orr[j] = fmaf(w[j][kk], vr, orr[j]);
            oii[j] = fmaf(w[j][kk], vi, oii[j]);
        }
    }
    const size_t dst = ((size_t)(b * TT + t0 + tid)) * C2K + h * 16;
    #pragma unroll
    for (int j = 0; j < 16; j += 4) {
        float4 v = {orr[j], orr[j+1], orr[j+2], orr[j+3]};
        *(float4*)(eig + dst + j) = v;
        float4 u = {oii[j], oii[j+1], oii[j+2], oii[j+3]};
        *(float4*)(eig + dst + KK + j) = u;
        uint2 vv = {h2u(__floats2half2_rn(orr[j], orr[j+1])),
                    h2u(__floats2half2_rn(orr[j+2], orr[j+3]))};
        *(uint2*)(eig_h + dst + j) = vv;
        uint2 uu = {h2u(__floats2half2_rn(oii[j], oii[j+1])),
                    h2u(__floats2half2_rn(oii[j+2], oii[j+3]))};
        *(uint2*)(eig_h + dst + KK + j) = uu;
    }
}

// ---------------- launch -----------------------------------------------------
extern "C" void kernel_launch(void* const* d_in, const int* in_sizes, int n_in,
                              void* d_out, int out_size)
{
    const float* x          = (const float*)d_in[0];
    const float* prev_eig   = (const float*)d_in[1];
    const float* in_proj_w  = (const float*)d_in[2];
    const float* conv_w     = (const float*)d_in[3];
    const float* conv_b     = (const float*)d_in[4];
    const float* mem_gate   = (const float*)d_in[5];
    const float* mem_proj_w = (const float*)d_in[6];
    const float* log_decay  = (const float*)d_in[7];
    const float* frequency  = (const float*)d_in[8];
    const float* coupling   = (const float*)d_in[9];
    const float* out_proj_w = (const float*)d_in[10];
    const float* gate_w     = (const float*)d_in[11];
    const float* gate_b     = (const float*)d_in[12];
    const float* mlp_w1     = (const float*)d_in[13];
    const float* mlp_b1     = (const float*)d_in[14];
    const float* mlp_w2     = (const float*)d_in[15];
    const float* mlp_b2     = (const float*)d_in[16];
    const float* n1_g       = (const float*)d_in[17];
    const float* n1_b       = (const float*)d_in[18];
    const float* n2_g       = (const float*)d_in[19];
    const float* n2_b       = (const float*)d_in[20];

    float* out_x2  = (float*)d_out;
    float* out_eig = out_x2 + (size_t)NT * DD;

    __half *xn_h, *y_h, *h1_h, *eig_h, *pe_h, *sig_h, *wh;
    float *beta0, *pm, *cRp, *cIp, *x1;
    cudaGetSymbolAddress((void**)&xn_h,  g_xn_h);
    cudaGetSymbolAddress((void**)&y_h,   g_y_h);
    cudaGetSymbolAddress((void**)&h1_h,  g_h1_h);
    cudaGetSymbolAddress((void**)&eig_h, g_eig_h);
    cudaGetSymbolAddress((void**)&pe_h,  g_pe_h);
    cudaGetSymbolAddress((void**)&sig_h, g_sig_h);
    cudaGetSymbolAddress((void**)&wh,    g_wh);
    cudaGetSymbolAddress((void**)&beta0, g_beta0);
    cudaGetSymbolAddress((void**)&pm,    g_pm);
    cudaGetSymbolAddress((void**)&cRp,   g_cR);
    cudaGetSymbolAddress((void**)&cIp,   g_cI);
    cudaGetSymbolAddress((void**)&x1,    g_x1);

    cudaFuncSetAttribute(mma_gemm<EPI_NONE>,     cudaFuncAttributeMaxDynamicSharedMemorySize, GEMM_SMEM);
    cudaFuncSetAttribute(mma_gemm<EPI_IPGATE>,   cudaFuncAttributeMaxDynamicSharedMemorySize, GEMM_SMEM);
    cudaFuncSetAttribute(mma_gemm<EPI_GATE>,     cudaFuncAttributeMaxDynamicSharedMemorySize, GEMM_SMEM);
    cudaFuncSetAttribute(mma_gemm<EPI_SILU_H>,   cudaFuncAttributeMaxDynamicSharedMemorySize, GEMM_SMEM);
    cudaFuncSetAttribute(mma_gemm<EPI_BIAS_RES>, cudaFuncAttributeMaxDynamicSharedMemorySize, GEMM_SMEM);

    CvtArgs ca;
    ca.src[0] = in_proj_w;  ca.dst[0] = wh + W_IPGATE;           ca.n8[0] = (int)((size_t)C2K * DD / 8);
    ca.src[1] = gate_w;     ca.dst[1] = wh + W_IPGATE + C2K*DD;  ca.n8[1] = (int)((size_t)DD * DD / 8);
    ca.src[2] = mem_proj_w; ca.dst[2] = wh + W_MEMPROJ;          ca.n8[2] = (int)((size_t)C2K * C2K / 8);
    ca.src[3] = out_proj_w; ca.dst[3] = wh + W_OUTPROJ;          ca.n8[3] = (int)((size_t)DD * C2K / 8);
    ca.src[4] = mlp_w1;     ca.dst[4] = wh + W_MLP1;             ca.n8[4] = (int)((size_t)MM * DD / 8);
    ca.src[5] = mlp_w2;     ca.dst[5] = wh + W_MLP2;             ca.n8[5] = (int)((size_t)DD * MM / 8);
    ca.src[6] = prev_eig;   ca.dst[6] = pe_h;                    ca.n8[6] = (int)((size_t)NT * C2K / 8);
    cvt_all_kernel<<<dim3(2048, 7), 256>>>(ca);

    // 1) pm = prev_eig @ mem_proj_w^T
    mma_gemm<EPI_NONE><<<dim3(C2K/128, NT/128), 256, GEMM_SMEM>>>(
        pe_h, wh + W_MEMPROJ, pm, NT, C2K, C2K, nullptr, nullptr, nullptr, nullptr);

    // 2) LN1 -> fp16
    ten_ln_kernel<<<NT, 256>>>(x, n1_g, n1_b, xn_h);

    // 3) fused in_proj + gate
    mma_gemm<EPI_IPGATE><<<dim3(1280/128, NT/128), 256, GEMM_SMEM>>>(
        xn_h, wh + W_IPGATE, beta0, NT, 1280, DD, gate_b, nullptr, nullptr, sig_h);

    // 4) fused conv + mem inject + scan
    ten_convscan_kernel<<<BB * KK, 256>>>(
        beta0, pm, conv_w, conv_b, mem_gate, log_decay, frequency, cRp, cIp);

    // 5) coupling -> eig fp32 (output) + fp16 copy
    ten_coupling_kernel<<<dim3(TT/256, HH, BB), 256>>>(cRp, cIp, coupling, out_eig, eig_h);

    // 6) x1 = x + sig * (eig @ out_proj^T)
    mma_gemm<EPI_GATE><<<dim3(DD/128, NT/128), 256, GEMM_SMEM>>>(
        eig_h, wh + W_OUTPROJ, x1, NT, DD, C2K, nullptr, sig_h, x, nullptr);

    // 7) LN2 -> fp16
    ten_ln_kernel<<<NT, 256>>>(x1, n2_g, n2_b, y_h);

    // 8) h1 = silu(y @ w1^T + b1) fp16
    mma_gemm<EPI_SILU_H><<<dim3(MM/128, NT/128), 256, GEMM_SMEM>>>(
        y_h, wh + W_MLP1, h1_h, NT, MM, DD, mlp_b1, nullptr, nullptr, nullptr);

    // 9) x2 = x1 + h1 @ w2^T + b2
    mma_gemm<EPI_BIAS_RES><<<dim3(DD/128, NT/128), 256, GEMM_SMEM>>>(
        h1_h, wh + W_MLP2, out_x2, NT, DD, MM, mlp_b2, nullptr, x1, nullptr);
}

// round 9
// speedup vs baseline: 1.0169x; 1.0127x over previous
#include <cuda_runtime.h>
#include <cuda_fp16.h>
#include <math.h>
#include <stdint.h>

// ---------------- problem constants ----------------
#define BB 4
#define TT 4096
#define DD 1024
#define KK 128
#define HH 8
#define KER 4
#define MM 4096          // mlp hidden
#define C2K 256          // 2*K
#define NT (BB*TT)       // 16384 rows

// ---------------- scratch (static device, no allocs) ----------------
__device__ __half g_xn_h[(size_t)NT*DD];     // LN1 out fp16
__device__ __half g_y_h[(size_t)NT*DD];      // LN2 out fp16
__device__ __half g_h1_h[(size_t)NT*MM];     // mlp mid fp16
__device__ __half g_eig_h[(size_t)NT*C2K];   // fp16 copy of eig
__device__ __half g_pe_h[(size_t)NT*C2K];    // fp16 prev_eig
__device__ __half g_sig_h[(size_t)NT*DD];    // sigmoid gate fp16
__device__ float  g_beta0[(size_t)NT*C2K];
__device__ float  g_pm[(size_t)NT*C2K];
__device__ float  g_bR[(size_t)BB*KK*TT];
__device__ float  g_bI[(size_t)BB*KK*TT];
__device__ float  g_cR[(size_t)BB*KK*TT];
__device__ float  g_cI[(size_t)BB*KK*TT];
__device__ float  g_x1[(size_t)NT*DD];
// fp16 weights, packed
#define W_INPROJ  0
#define W_MEMPROJ (W_INPROJ + C2K*DD)
#define W_OUTPROJ (W_MEMPROJ + C2K*C2K)
#define W_GATE    (W_OUTPROJ + DD*C2K)
#define W_MLP1    (W_GATE + DD*DD)
#define W_MLP2    (W_MLP1 + (size_t)MM*DD)
#define W_TOTAL   (W_MLP2 + (size_t)DD*MM)
__device__ __half g_wh[W_TOTAL];

__device__ __forceinline__ float sigmf(float x) { return 1.f / (1.f + __expf(-x)); }
__device__ __forceinline__ uint32_t smem_u32(const void* p) {
    uint32_t a;
    asm("{ .reg .u64 t; cvta.to.shared.u64 t, %1; cvt.u32.u64 %0, t; }" : "=r"(a) : "l"(p));
    return a;
}
__device__ __forceinline__ void cp16(uint32_t s, const void* g) {
    asm volatile("cp.async.cg.shared.global [%0], [%1], 16;" :: "r"(s), "l"(g));
}
__device__ __forceinline__ uint32_t h2u(__half2 h) { return *(uint32_t*)&h; }
__device__ __forceinline__ void ldsm_x4(uint32_t& r0, uint32_t& r1, uint32_t& r2, uint32_t& r3,
                                        uint32_t addr) {
    asm volatile("ldmatrix.sync.aligned.m8n8.x4.shared.b16 {%0,%1,%2,%3}, [%4];"
                 : "=r"(r0), "=r"(r1), "=r"(r2), "=r"(r3) : "r"(addr));
}

// ============================ batched fp32 -> fp16 ============================
struct CvtArgs {
    const float* src[7];
    __half* dst[7];
    int n8[7];
};
__global__ void cvt_all_kernel(CvtArgs a)
{
    const int seg = blockIdx.y;
    const int i = blockIdx.x * blockDim.x + threadIdx.x;
    if (i < a.n8[seg]) {
        const float4* s4 = (const float4*)a.src[seg] + 2 * (size_t)i;
        float4 p = s4[0], q = s4[1];
        uint4 o = {h2u(__floats2half2_rn(p.x, p.y)), h2u(__floats2half2_rn(p.z, p.w)),
                   h2u(__floats2half2_rn(q.x, q.y)), h2u(__floats2half2_rn(q.z, q.w))};
        ((uint4*)a.dst[seg])[i] = o;
    }
}

// ============================ LayerNorm -> fp16 out ============================
__global__ void ten_ln_kernel(const float* __restrict__ x,
                              const float* __restrict__ gw,
                              const float* __restrict__ bw,
                              __half* __restrict__ yh)
{
    const int row = blockIdx.x;
    const int tid = threadIdx.x;
    const float4* xr = (const float4*)(x + (size_t)row * DD);
    float4 v = xr[tid];
    float s = v.x + v.y + v.z + v.w;
    float q = v.x*v.x + v.y*v.y + v.z*v.z + v.w*v.w;
    #pragma unroll
    for (int o = 16; o > 0; o >>= 1) {
        s += __shfl_xor_sync(0xffffffffu, s, o);
        q += __shfl_xor_sync(0xffffffffu, q, o);
    }
    __shared__ float ss[8], sq[8];
    const int w = tid >> 5, l = tid & 31;
    if (l == 0) { ss[w] = s; sq[w] = q; }
    __syncthreads();
    float st = 0.f, qt = 0.f;
    #pragma unroll
    for (int i = 0; i < 8; i++) { st += ss[i]; qt += sq[i]; }
    const float mean = st * (1.f / DD);
    const float var  = qt * (1.f / DD) - mean * mean;
    const float rstd = rsqrtf(var + 1e-5f);
    float4 g4 = ((const float4*)gw)[tid];
    float4 b4 = ((const float4*)bw)[tid];
    float ox = (v.x - mean) * rstd * g4.x + b4.x;
    float oy = (v.y - mean) * rstd * g4.y + b4.y;
    float oz = (v.z - mean) * rstd * g4.z + b4.z;
    float ow = (v.w - mean) * rstd * g4.w + b4.w;
    uint2 ov = {h2u(__floats2half2_rn(ox, oy)), h2u(__floats2half2_rn(oz, ow))};
    ((uint2*)(yh + (size_t)row * DD))[tid] = ov;
}

// ============================ fp16 mma.sync GEMM ============================
// C[M,N] = A[M,K] @ B[N,K]^T ; block 128x128, BK=64 halves, 3-stage cp.async,
// 8 warps (2x4), warp tile 64x32, cp.async spread across ks loop, 2 CTAs/SM.
enum { EPI_NONE = 0, EPI_SIG = 1, EPI_GATE = 2, EPI_SILU_H = 3, EPI_BIAS_RES = 4 };

#define ASTR 36                    // b32 per SMEM row (32 data + 4 pad)
#define ROWB (ASTR*4)              // 144 bytes per row
#define A_B32 (128*ASTR)
#define B_B32 (128*ASTR)
#define ST_B32 (A_B32 + B_B32)     // 9216 b32
#define GEMM_SMEM (3*ST_B32*4)     // 110592 B

template<int EPI>
__global__ void __launch_bounds__(256, 2)
mma_gemm(const __half* __restrict__ A, const __half* __restrict__ B, void* Cv,
         int M, int N, int K,
         const float* __restrict__ aux0, const void* __restrict__ aux1,
         const float* __restrict__ aux2)
{
    extern __shared__ uint32_t smu[];
    const uint32_t sm_base = smem_u32(smu);
    const int tid = threadIdx.x;
    const int lane = tid & 31, wid = tid >> 5;
    const int wm = wid >> 2, wn = wid & 3;          // 2 x 4 warp grid
    const int m0 = blockIdx.y * 128, n0 = blockIdx.x * 128;
    const int nchunk = K >> 6;
    const int g = lane >> 2, t = lane & 3;

    const __half* Ag = A + (size_t)m0 * K;
    const __half* Bg = B + (size_t)n0 * K;

    // per-thread cp.async geometry: u constant, r = r0 + 32*ks
    const int r0 = tid >> 3;            // 0..31
    const int u  = tid & 7;             // 0..7
    const uint32_t cpSmA0 = (uint32_t)(r0 * ASTR + u * 4) * 4;
    const uint32_t cpSmB0 = (uint32_t)(A_B32 + r0 * ASTR + u * 4) * 4;
    const uint32_t cpSmStep = (uint32_t)(32 * ASTR) * 4;

    auto load_stage = [&](int s, int c) {
        const uint32_t sb = sm_base + (uint32_t)(s * ST_B32) * 4;
        const __half* ac = Ag + (size_t)c * 64;
        const __half* bc = Bg + (size_t)c * 64;
        #pragma unroll
        for (int j = 0; j < 4; j++) {
            const int r = r0 + j * 32;
            cp16(sb + cpSmA0 + j * cpSmStep, ac + (size_t)r * K + u * 8);
            cp16(sb + cpSmB0 + j * cpSmStep, bc + (size_t)r * K + u * 8);
        }
        asm volatile("cp.async.commit_group;");
    };

    float acc[4][4][4];
    #pragma unroll
    for (int mi = 0; mi < 4; mi++)
        #pragma unroll
        for (int ni = 0; ni < 4; ni++)
            #pragma unroll
            for (int q = 0; q < 4; q++) acc[mi][ni][q] = 0.f;

    load_stage(0, 0);
    if (1 < nchunk) load_stage(1, 1);

    const uint32_t aOff = (uint32_t)(wm * 64 + (lane & 15)) * ROWB + (uint32_t)(lane >> 4) * 16;
    const uint32_t bOff = (uint32_t)A_B32 * 4 +
        (uint32_t)(wn * 32 + (lane & 7) + ((lane >> 4) & 1) * 8) * ROWB +
        (uint32_t)((lane >> 3) & 1) * 16;

    int stage = 0;
    for (int i = 0; i < nchunk; i++) {
        if (i == nchunk - 1) asm volatile("cp.async.wait_group 0;" ::: "memory");
        else                 asm volatile("cp.async.wait_group 1;" ::: "memory");
        __syncthreads();

        // prefetch targets for chunk i+2 (issued spread across ks loop)
        const bool pf = (i + 2 < nchunk);
        int ns = stage + 2; if (ns >= 3) ns -= 3;
        const uint32_t pfSb = sm_base + (uint32_t)(ns * ST_B32) * 4;
        const __half* pfA = Ag + (size_t)(i + 2) * 64 + (size_t)r0 * K + u * 8;
        const __half* pfB = Bg + (size_t)(i + 2) * 64 + (size_t)r0 * K + u * 8;

        const uint32_t stBase = sm_base + (uint32_t)(stage * ST_B32) * 4;
        #pragma unroll
        for (int ks = 0; ks < 4; ks++) {
            const uint32_t kb = (uint32_t)ks * 32;
            uint32_t af[4][4], bf[4][2];
            #pragma unroll
            for (int mi = 0; mi < 4; mi++)
                ldsm_x4(af[mi][0], af[mi][1], af[mi][2], af[mi][3],
                        stBase + aOff + (uint32_t)mi * (16 * ROWB) + kb);
            #pragma unroll
            for (int np = 0; np < 2; np++)
                ldsm_x4(bf[2*np][0], bf[2*np][1], bf[2*np+1][0], bf[2*np+1][1],
                        stBase + bOff + (uint32_t)np * (16 * ROWB) + kb);
            if (pf) {
                // one A-quarter + one B-quarter of chunk i+2 per ks step
                cp16(pfSb + cpSmA0 + (uint32_t)ks * cpSmStep, pfA + (size_t)(ks * 32) * K);
                cp16(pfSb + cpSmB0 + (uint32_t)ks * cpSmStep, pfB + (size_t)(ks * 32) * K);
            }
            #pragma unroll
            for (int mi = 0; mi < 4; mi++)
                #pragma unroll
                for (int ni = 0; ni < 4; ni++)
                    asm volatile(
                        "mma.sync.aligned.m16n8k16.row.col.f32.f16.f16.f32 "
                        "{%0,%1,%2,%3}, {%4,%5,%6,%7}, {%8,%9}, {%0,%1,%2,%3};"
                        : "+f"(acc[mi][ni][0]), "+f"(acc[mi][ni][1]),
                          "+f"(acc[mi][ni][2]), "+f"(acc[mi][ni][3])
                        : "r"(af[mi][0]), "r"(af[mi][1]), "r"(af[mi][2]), "r"(af[mi][3]),
                          "r"(bf[ni][0]), "r"(bf[ni][1]));
        }
        if (pf) asm volatile("cp.async.commit_group;");
        if (++stage == 3) stage = 0;
    }

    // -------- epilogue --------
    float* Cf = (float*)Cv;
    __half* Ch = (__half*)Cv;
    const __half* sgh = (const __half*)aux1;   // EPI_GATE: fp16 sigmoid gate
    #pragma unroll
    for (int mi = 0; mi < 4; mi++) {
        const int rbase = m0 + wm * 64 + mi * 16 + g;
        #pragma unroll
        for (int ni = 0; ni < 4; ni++) {
            const int cc = n0 + wn * 32 + ni * 8 + t * 2;
            #pragma unroll
            for (int half_ = 0; half_ < 2; half_++) {
                const int r = rbase + half_ * 8;
                float v0 = acc[mi][ni][half_ * 2 + 0];
                float v1 = acc[mi][ni][half_ * 2 + 1];
                const size_t off = (size_t)r * N + cc;
                if (EPI == EPI_NONE) {
                    float2 o = {v0, v1};
                    *(float2*)(Cf + off) = o;
                } else if (EPI == EPI_SIG) {
                    float2 gb = *(const float2*)(aux0 + cc);
                    __half2 o = __floats2half2_rn(sigmf(v0 + gb.x), sigmf(v1 + gb.y));
                    *(uint32_t*)(Ch + off) = h2u(o);
                } else if (EPI == EPI_GATE) {
                    uint32_t su = *(const uint32_t*)(sgh + off);
                    float2 sg = __half22float2(*(__half2*)&su);
                    float2 xr = *(const float2*)(aux2 + off);
                    float2 o = {xr.x + sg.x * v0, xr.y + sg.y * v1};
                    *(float2*)(Cf + off) = o;
                } else if (EPI == EPI_SILU_H) {
                    float2 bb = *(const float2*)(aux0 + cc);
                    float t0 = v0 + bb.x, t1 = v1 + bb.y;
                    __half2 o = __floats2half2_rn(t0 * sigmf(t0), t1 * sigmf(t1));
                    *(uint32_t*)(Ch + off) = h2u(o);
                } else if (EPI == EPI_BIAS_RES) {
                    float2 bb = *(const float2*)(aux0 + cc);
                    float2 xr = *(const float2*)(aux2 + off);
                    float2 o = {xr.x + v0 + bb.x, xr.y + v1 + bb.y};
                    *(float2*)(Cf + off) = o;
                }
            }
        }
    }
}

// ---------------- depthwise causal conv + bias + SiLU + mem inject ----------
__global__ void __launch_bounds__(256)
ten_conv_mem_kernel(const float* __restrict__ beta0,
                    const float* __restrict__ pm,
                    const float* __restrict__ conv_w,
                    const float* __restrict__ conv_b,
                    const float* __restrict__ mem_gate,
                    float* __restrict__ bR, float* __restrict__ bI)
{
    const int b   = blockIdx.z;
    const int cg0 = blockIdx.y * 32;
    const int t0  = blockIdx.x * 64;
    __shared__ float sb[67][33];
    __shared__ float sp[64][33];
    const int tid = threadIdx.x;

    for (int i = tid; i < 67 * 32; i += 256) {
        const int r = i >> 5, c = i & 31;
        const int t = t0 + r - 3;
        sb[r][c] = (t >= 0) ? beta0[((size_t)(b * TT + t)) * C2K + cg0 + c] : 0.f;
    }
    for (int i = tid; i < 64 * 32; i += 256) {
        const int r = i >> 5, c = i & 31;
        sp[r][c] = pm[((size_t)(b * TT + t0 + r)) * C2K + cg0 + c];
    }
    __syncthreads();

    const float mg = 1.f / (1.f + expf(-mem_gate[0]));
    const int cl = tid >> 3;
    const int tg = (tid & 7) * 8;
    const int cglob = cg0 + cl;
    const float w0 = conv_w[cglob * 4 + 0];
    const float w1 = conv_w[cglob * 4 + 1];
    const float w2 = conv_w[cglob * 4 + 2];
    const float w3 = conv_w[cglob * 4 + 3];
    const float cb = conv_b[cglob];
    const int k = cglob & (KK - 1);
    float* dst = ((cglob < KK) ? bR : bI) + ((size_t)(b * KK + k)) * TT + t0 + tg;
    #pragma unroll
    for (int j = 0; j < 8; j++) {
        const int r = tg + j;
        float v = sb[r][cl] * w0 + sb[r + 1][cl] * w1 + sb[r + 2][cl] * w2 + sb[r + 3][cl] * w3 + cb;
        v = v * (1.f / (1.f + __expf(-v)));
        v += mg * sp[r][cl];
        dst[j] = v;
    }
}

// ---------------- complex first-order recurrence scan -----------------------
__global__ void __launch_bounds__(256)
ten_scan_kernel(const float* __restrict__ bR, const float* __restrict__ bI,
                const float* __restrict__ log_decay, const float* __restrict__ freq,
                float* __restrict__ cR, float* __restrict__ cI)
{
    const int bk = blockIdx.x;
    const int k = bk & (KK - 1);
    const float mag = 1.f / (1.f + expf(-log_decay[k]));
    float snf, csf;
    sincosf(freq[k], &snf, &csf);
    const float lr = mag * csf, li = mag * snf;
    const int tid = threadIdx.x;
    const size_t base = (size_t)bk * TT + tid * 16;

    float xr[16], xi[16];
    #pragma unroll
    for (int v = 0; v < 4; v++) {
        float4 a = *(const float4*)(bR + base + v * 4);
        xr[v*4+0] = a.x; xr[v*4+1] = a.y; xr[v*4+2] = a.z; xr[v*4+3] = a.w;
        float4 c = *(const float4*)(bI + base + v * 4);
        xi[v*4+0] = c.x; xi[v*4+1] = c.y; xi[v*4+2] = c.z; xi[v*4+3] = c.w;
    }

    float cr = 0.f, ci = 0.f;
    #pragma unroll
    for (int j = 0; j < 16; j++) {
        float nr = fmaf(lr, cr, fmaf(-li, ci, xr[j]));
        float ni = fmaf(lr, ci, fmaf( li, cr, xi[j]));
        cr = nr; ci = ni;
        xr[j] = cr; xi[j] = ci;
    }

    float fr = lr, fi = li;
    #pragma unroll
    for (int s = 0; s < 4; s++) {
        float nr = fr * fr - fi * fi;
        float ni = 2.f * fr * fi;
        fr = nr; fi = ni;
    }

    __shared__ float sgr[256], sgi[256], sor[256], soi[256];
    sgr[tid] = fr; sgi[tid] = fi; sor[tid] = cr; soi[tid] = ci;
    __syncthreads();
    for (int d = 1; d < 256; d <<= 1) {
        float ngr = 0.f, ngi = 0.f, nor_ = 0.f, noi_ = 0.f;
        if (tid >= d) {
            const float pgr = sgr[tid - d], pgi = sgi[tid - d];
            const float por = sor[tid - d], poi = soi[tid - d];
            const float gr = sgr[tid], gi = sgi[tid];
            const float orr = sor[tid], oii = soi[tid];
            ngr  = gr * pgr - gi * pgi;
            ngi  = gr * pgi + gi * pgr;
            nor_ = gr * por - gi * poi + orr;
            noi_ = gr * poi + gi * por + oii;
        }
        __syncthreads();
        if (tid >= d) { sgr[tid] = ngr; sgi[tid] = ngi; sor[tid] = nor_; soi[tid] = noi_; }
        __syncthreads();
    }
    const float pr = (tid > 0) ? sor[tid - 1] : 0.f;
    const float pi = (tid > 0) ? soi[tid - 1] : 0.f;

    float lpr = lr, lpi = li;
    #pragma unroll
    for (int j = 0; j < 16; j++) {
        xr[j] = fmaf(lpr, pr, fmaf(-lpi, pi, xr[j]));
        xi[j] = fmaf(lpr, pi, fmaf( lpi, pr, xi[j]));
        float nr = lpr * lr - lpi * li;
        float ni = lpr * li + lpi * lr;
        lpr = nr; lpi = ni;
    }
    #pragma unroll
    for (int v = 0; v < 4; v++) {
        float4 a = {xr[v*4+0], xr[v*4+1], xr[v*4+2], xr[v*4+3]};
        *(float4*)(cR + base + v * 4) = a;
        float4 c = {xi[v*4+0], xi[v*4+1], xi[v*4+2], xi[v*4+3]};
        *(float4*)(cI + base + v * 4) = c;
    }
}

// ---------------- coupling + transpose -> eig fp32 (output) + fp16 copy -----
__global__ void __launch_bounds__(256)
ten_coupling_kernel(const float* __restrict__ cR, const float* __restrict__ cI,
                    const float* __restrict__ coupling,
                    float* __restrict__ eig, __half* __restrict__ eig_h)
{
    const int b = blockIdx.z, h = blockIdx.y;
    const int t0 = blockIdx.x * 256;
    const int tid = threadIdx.x;
    __shared__ float sr[16][256];
    __shared__ float si[16][256];
    __shared__ float w[16][16];
    w[tid >> 4][tid & 15] = coupling[h * 256 + tid];
    #pragma unroll
    for (int kk = 0; kk < 16; kk++) {
        const size_t src = ((size_t)(b * KK + h * 16 + kk)) * TT + t0 + tid;
        sr[kk][tid] = cR[src];
        si[kk][tid] = cI[src];
    }
    __syncthreads();
    float orr[16], oii[16];
    #pragma unroll
    for (int j = 0; j < 16; j++) { orr[j] = 0.f; oii[j] = 0.f; }
    #pragma unroll
    for (int kk = 0; kk < 16; kk++) {
        const float vr = sr[kk][tid];
        const float vi = si[kk][tid];
        #pragma unroll
        for (int j = 0; j < 16; j++) {
            orr[j] = fmaf(w[j][kk], vr, orr[j]);
            oii[j] = fmaf(w[j][kk], vi, oii[j]);
        }
    }
    const size_t dst = ((size_t)(b * TT + t0 + tid)) * C2K + h * 16;
    #pragma unroll
    for (int j = 0; j < 16; j += 4) {
        float4 v = {orr[j], orr[j+1], orr[j+2], orr[j+3]};
        *(float4*)(eig + dst + j) = v;
        float4 u = {oii[j], oii[j+1], oii[j+2], oii[j+3]};
        *(float4*)(eig + dst + KK + j) = u;
        uint2 vv = {h2u(__floats2half2_rn(orr[j], orr[j+1])),
                    h2u(__floats2half2_rn(orr[j+2], orr[j+3]))};
        *(uint2*)(eig_h + dst + j) = vv;
        uint2 uu = {h2u(__floats2half2_rn(oii[j], oii[j+1])),
                    h2u(__floats2half2_rn(oii[j+2], oii[j+3]))};
        *(uint2*)(eig_h + dst + KK + j) = uu;
    }
}

// ---------------- launch -----------------------------------------------------
extern "C" void kernel_launch(void* const* d_in, const int* in_sizes, int n_in,
                              void* d_out, int out_size)
{
    const float* x          = (const float*)d_in[0];
    const float* prev_eig   = (const float*)d_in[1];
    const float* in_proj_w  = (const float*)d_in[2];
    const float* conv_w     = (const float*)d_in[3];
    const float* conv_b     = (const float*)d_in[4];
    const float* mem_gate   = (const float*)d_in[5];
    const float* mem_proj_w = (const float*)d_in[6];
    const float* log_decay  = (const float*)d_in[7];
    const float* frequency  = (const float*)d_in[8];
    const float* coupling   = (const float*)d_in[9];
    const float* out_proj_w = (const float*)d_in[10];
    const float* gate_w     = (const float*)d_in[11];
    const float* gate_b     = (const float*)d_in[12];
    const float* mlp_w1     = (const float*)d_in[13];
    const float* mlp_b1     = (const float*)d_in[14];
    const float* mlp_w2     = (const float*)d_in[15];
    const float* mlp_b2     = (const float*)d_in[16];
    const float* n1_g       = (const float*)d_in[17];
    const float* n1_b       = (const float*)d_in[18];
    const float* n2_g       = (const float*)d_in[19];
    const float* n2_b       = (const float*)d_in[20];

    float* out_x2  = (float*)d_out;
    float* out_eig = out_x2 + (size_t)NT * DD;

    __half *xn_h, *y_h, *h1_h, *eig_h, *pe_h, *sig_h, *wh;
    float *beta0, *pm, *bRp, *bIp, *cRp, *cIp, *x1;
    cudaGetSymbolAddress((void**)&xn_h,  g_xn_h);
    cudaGetSymbolAddress((void**)&y_h,   g_y_h);
    cudaGetSymbolAddress((void**)&h1_h,  g_h1_h);
    cudaGetSymbolAddress((void**)&eig_h, g_eig_h);
    cudaGetSymbolAddress((void**)&pe_h,  g_pe_h);
    cudaGetSymbolAddress((void**)&sig_h, g_sig_h);
    cudaGetSymbolAddress((void**)&wh,    g_wh);
    cudaGetSymbolAddress((void**)&beta0, g_beta0);
    cudaGetSymbolAddress((void**)&pm,    g_pm);
    cudaGetSymbolAddress((void**)&bRp,   g_bR);
    cudaGetSymbolAddress((void**)&bIp,   g_bI);
    cudaGetSymbolAddress((void**)&cRp,   g_cR);
    cudaGetSymbolAddress((void**)&cIp,   g_cI);
    cudaGetSymbolAddress((void**)&x1,    g_x1);

    cudaFuncSetAttribute(mma_gemm<EPI_NONE>,     cudaFuncAttributeMaxDynamicSharedMemorySize, GEMM_SMEM);
    cudaFuncSetAttribute(mma_gemm<EPI_SIG>,      cudaFuncAttributeMaxDynamicSharedMemorySize, GEMM_SMEM);
    cudaFuncSetAttribute(mma_gemm<EPI_GATE>,     cudaFuncAttributeMaxDynamicSharedMemorySize, GEMM_SMEM);
    cudaFuncSetAttribute(mma_gemm<EPI_SILU_H>,   cudaFuncAttributeMaxDynamicSharedMemorySize, GEMM_SMEM);
    cudaFuncSetAttribute(mma_gemm<EPI_BIAS_RES>, cudaFuncAttributeMaxDynamicSharedMemorySize, GEMM_SMEM);

    // batched weight/activation conversion (7 segments, one launch)
    CvtArgs ca;
    ca.src[0] = in_proj_w;  ca.dst[0] = wh + W_INPROJ;  ca.n8[0] = (int)((size_t)C2K * DD / 8);
    ca.src[1] = mem_proj_w; ca.dst[1] = wh + W_MEMPROJ; ca.n8[1] = (int)((size_t)C2K * C2K / 8);
    ca.src[2] = out_proj_w; ca.dst[2] = wh + W_OUTPROJ; ca.n8[2] = (int)((size_t)DD * C2K / 8);
    ca.src[3] = gate_w;     ca.dst[3] = wh + W_GATE;    ca.n8[3] = (int)((size_t)DD * DD / 8);
    ca.src[4] = mlp_w1;     ca.dst[4] = wh + W_MLP1;    ca.n8[4] = (int)((size_t)MM * DD / 8);
    ca.src[5] = mlp_w2;     ca.dst[5] = wh + W_MLP2;    ca.n8[5] = (int)((size_t)DD * MM / 8);
    ca.src[6] = prev_eig;   ca.dst[6] = pe_h;           ca.n8[6] = (int)((size_t)NT * C2K / 8);
    cvt_all_kernel<<<dim3(2048, 7), 256>>>(ca);

    // 1) pm = prev_eig @ mem_proj_w^T (independent of LN1)
    mma_gemm<EPI_NONE><<<dim3(C2K/128, NT/128), 256, GEMM_SMEM>>>(
        pe_h, wh + W_MEMPROJ, pm, NT, C2K, C2K, nullptr, nullptr, nullptr);

    // 2) LN1 -> fp16
    ten_ln_kernel<<<NT, 256>>>(x, n1_g, n1_b, xn_h);

    // 3) beta0 = xn @ in_proj_w^T
    mma_gemm<EPI_NONE><<<dim3(C2K/128, NT/128), 256, GEMM_SMEM>>>(
        xn_h, wh + W_INPROJ, beta0, NT, C2K, DD, nullptr, nullptr, nullptr);
    // 4) gate sigmoid -> fp16
    mma_gemm<EPI_SIG><<<dim3(DD/128, NT/128), 256, GEMM_SMEM>>>(
        xn_h, wh + W_GATE, sig_h, NT, DD, DD, gate_b, nullptr, nullptr);

    // 5) conv + SiLU + mem inject (smem-staged, coalesced)
    ten_conv_mem_kernel<<<dim3(TT/64, C2K/32, BB), 256>>>(
        beta0, pm, conv_w, conv_b, mem_gate, bRp, bIp);
    // 6) recurrence scan
    ten_scan_kernel<<<BB * KK, 256>>>(bRp, bIp, log_decay, frequency, cRp, cIp);
    // 7) coupling -> eig fp32 (output) + fp16 copy
    ten_coupling_kernel<<<dim3(TT/256, HH, BB), 256>>>(cRp, cIp, coupling, out_eig, eig_h);

    // 8) x1 = x + sig * (eig @ out_proj^T)
    mma_gemm<EPI_GATE><<<dim3(DD/128, NT/128), 256, GEMM_SMEM>>>(
        eig_h, wh + W_OUTPROJ, x1, NT, DD, C2K, nullptr, sig_h, x);

    // 9) LN2 -> fp16
    ten_ln_kernel<<<NT, 256>>>(x1, n2_g, n2_b, y_h);

    // 10) h1 = silu(y @ w1^T + b1) fp16
    mma_gemm<EPI_SILU_H><<<dim3(MM/128, NT/128), 256, GEMM_SMEM>>>(
        y_h, wh + W_MLP1, h1_h, NT, MM, DD, mlp_b1, nullptr, nullptr);
    // 11) x2 = x1 + h1 @ w2^T + b2
    mma_gemm<EPI_BIAS_RES><<<dim3(DD/128, NT/128), 256, GEMM_SMEM>>>(
        h1_h, wh + W_MLP2, out_x2, NT, DD, MM, mlp_b2, nullptr, x1);
}

// round 10
// speedup vs baseline: 1.0279x; 1.0107x over previous
#include <cuda_runtime.h>
#include <cuda_fp16.h>
#include <math.h>
#include <stdint.h>

// ---------------- problem constants ----------------
#define BB 4
#define TT 4096
#define DD 1024
#define KK 128
#define HH 8
#define KER 4
#define MM 4096          // mlp hidden
#define C2K 256          // 2*K
#define NT (BB*TT)       // 16384 rows

// ---------------- scratch (static device, no allocs) ----------------
__device__ __half g_xn_h[(size_t)NT*DD];     // LN1 out fp16
__device__ __half g_y_h[(size_t)NT*DD];      // LN2 out fp16
__device__ __half g_h1_h[(size_t)NT*MM];     // mlp mid fp16
__device__ __half g_eig_h[(size_t)NT*C2K];   // fp16 copy of eig
__device__ __half g_pe_h[(size_t)NT*C2K];    // fp16 prev_eig
__device__ __half g_sig_h[(size_t)NT*DD];    // sigmoid gate fp16
__device__ float  g_beta0[(size_t)NT*C2K];
__device__ float  g_pm[(size_t)NT*C2K];
__device__ float  g_bR[(size_t)BB*KK*TT];
__device__ float  g_bI[(size_t)BB*KK*TT];
__device__ float  g_cR[(size_t)BB*KK*TT];
__device__ float  g_cI[(size_t)BB*KK*TT];
__device__ float  g_x1[(size_t)NT*DD];
// fp16 weights, packed
#define W_INPROJ  0
#define W_MEMPROJ (W_INPROJ + C2K*DD)
#define W_OUTPROJ (W_MEMPROJ + C2K*C2K)
#define W_GATE    (W_OUTPROJ + DD*C2K)
#define W_MLP1    (W_GATE + DD*DD)
#define W_MLP2    (W_MLP1 + (size_t)MM*DD)
#define W_TOTAL   (W_MLP2 + (size_t)DD*MM)
__device__ __half g_wh[W_TOTAL];

__device__ __forceinline__ float sigmf(float x) { return 1.f / (1.f + __expf(-x)); }
__device__ __forceinline__ uint32_t smem_u32(const void* p) {
    uint32_t a;
    asm("{ .reg .u64 t; cvta.to.shared.u64 t, %1; cvt.u32.u64 %0, t; }" : "=r"(a) : "l"(p));
    return a;
}
__device__ __forceinline__ void cp16(uint32_t s, const void* g) {
    asm volatile("cp.async.cg.shared.global [%0], [%1], 16;" :: "r"(s), "l"(g));
}
__device__ __forceinline__ uint32_t h2u(__half2 h) { return *(uint32_t*)&h; }
__device__ __forceinline__ void ldsm_x4(uint32_t& r0, uint32_t& r1, uint32_t& r2, uint32_t& r3,
                                        uint32_t addr) {
    asm volatile("ldmatrix.sync.aligned.m8n8.x4.shared.b16 {%0,%1,%2,%3}, [%4];"
                 : "=r"(r0), "=r"(r1), "=r"(r2), "=r"(r3) : "r"(addr));
}

// ============================ batched fp32 -> fp16 ============================
struct CvtArgs {
    const float* src[7];
    __half* dst[7];
    int n8[7];
};
__global__ void cvt_all_kernel(CvtArgs a)
{
    const int seg = blockIdx.y;
    const int i = blockIdx.x * blockDim.x + threadIdx.x;
    if (i < a.n8[seg]) {
        const float4* s4 = (const float4*)a.src[seg] + 2 * (size_t)i;
        float4 p = s4[0], q = s4[1];
        uint4 o = {h2u(__floats2half2_rn(p.x, p.y)), h2u(__floats2half2_rn(p.z, p.w)),
                   h2u(__floats2half2_rn(q.x, q.y)), h2u(__floats2half2_rn(q.z, q.w))};
        ((uint4*)a.dst[seg])[i] = o;
    }
}

// ============================ LayerNorm -> fp16 out ============================
__global__ void ten_ln_kernel(const float* __restrict__ x,
                              const float* __restrict__ gw,
                              const float* __restrict__ bw,
                              __half* __restrict__ yh)
{
    const int row = blockIdx.x;
    const int tid = threadIdx.x;
    const float4* xr = (const float4*)(x + (size_t)row * DD);
    float4 v = xr[tid];
    float s = v.x + v.y + v.z + v.w;
    float q = v.x*v.x + v.y*v.y + v.z*v.z + v.w*v.w;
    #pragma unroll
    for (int o = 16; o > 0; o >>= 1) {
        s += __shfl_xor_sync(0xffffffffu, s, o);
        q += __shfl_xor_sync(0xffffffffu, q, o);
    }
    __shared__ float ss[8], sq[8];
    const int w = tid >> 5, l = tid & 31;
    if (l == 0) { ss[w] = s; sq[w] = q; }
    __syncthreads();
    float st = 0.f, qt = 0.f;
    #pragma unroll
    for (int i = 0; i < 8; i++) { st += ss[i]; qt += sq[i]; }
    const float mean = st * (1.f / DD);
    const float var  = qt * (1.f / DD) - mean * mean;
    const float rstd = rsqrtf(var + 1e-5f);
    float4 g4 = ((const float4*)gw)[tid];
    float4 b4 = ((const float4*)bw)[tid];
    float ox = (v.x - mean) * rstd * g4.x + b4.x;
    float oy = (v.y - mean) * rstd * g4.y + b4.y;
    float oz = (v.z - mean) * rstd * g4.z + b4.z;
    float ow = (v.w - mean) * rstd * g4.w + b4.w;
    uint2 ov = {h2u(__floats2half2_rn(ox, oy)), h2u(__floats2half2_rn(oz, ow))};
    ((uint2*)(yh + (size_t)row * DD))[tid] = ov;
}

// ============================ fp16 mma.sync GEMM ============================
enum { EPI_NONE = 0, EPI_SIG = 1, EPI_GATE = 2, EPI_SILU_H = 3, EPI_BIAS_RES = 4 };

#define ASTR 36                    // b32 per SMEM row (32 data + 4 pad)
#define ROWB (ASTR*4)              // 144 bytes per row
#define A_B32 (128*ASTR)
#define B_B32 (128*ASTR)
#define ST_B32 (A_B32 + B_B32)     // 9216 b32
#define GEMM_SMEM (3*ST_B32*4)     // 110592 B

template<int EPI>
__global__ void __launch_bounds__(256, 2)
mma_gemm(const __half* __restrict__ A, const __half* __restrict__ B, void* Cv,
         int M, int N, int K,
         const float* __restrict__ aux0, const void* __restrict__ aux1,
         const float* __restrict__ aux2)
{
    extern __shared__ uint32_t smu[];
    const uint32_t sm_base = smem_u32(smu);
    const int tid = threadIdx.x;
    const int lane = tid & 31, wid = tid >> 5;
    const int wm = wid >> 2, wn = wid & 3;          // 2 x 4 warp grid
    const int m0 = blockIdx.y * 128, n0 = blockIdx.x * 128;
    const int nchunk = K >> 6;
    const int g = lane >> 2, t = lane & 3;

    const __half* Ag = A + (size_t)m0 * K;
    const __half* Bg = B + (size_t)n0 * K;

    const int r0 = tid >> 3;            // 0..31
    const int u  = tid & 7;             // 0..7
    const uint32_t cpSmA0 = (uint32_t)(r0 * ASTR + u * 4) * 4;
    const uint32_t cpSmB0 = (uint32_t)(A_B32 + r0 * ASTR + u * 4) * 4;
    const uint32_t cpSmStep = (uint32_t)(32 * ASTR) * 4;

    auto load_stage = [&](int s, int c) {
        const uint32_t sb = sm_base + (uint32_t)(s * ST_B32) * 4;
        const __half* ac = Ag + (size_t)c * 64;
        const __half* bc = Bg + (size_t)c * 64;
        #pragma unroll
        for (int j = 0; j < 4; j++) {
            const int r = r0 + j * 32;
            cp16(sb + cpSmA0 + j * cpSmStep, ac + (size_t)r * K + u * 8);
            cp16(sb + cpSmB0 + j * cpSmStep, bc + (size_t)r * K + u * 8);
        }
        asm volatile("cp.async.commit_group;");
    };

    float acc[4][4][4];
    #pragma unroll
    for (int mi = 0; mi < 4; mi++)
        #pragma unroll
        for (int ni = 0; ni < 4; ni++)
            #pragma unroll
            for (int q = 0; q < 4; q++) acc[mi][ni][q] = 0.f;

    load_stage(0, 0);
    if (1 < nchunk) load_stage(1, 1);

    const uint32_t aOff = (uint32_t)(wm * 64 + (lane & 15)) * ROWB + (uint32_t)(lane >> 4) * 16;
    const uint32_t bOff = (uint32_t)A_B32 * 4 +
        (uint32_t)(wn * 32 + (lane & 7) + ((lane >> 4) & 1) * 8) * ROWB +
        (uint32_t)((lane >> 3) & 1) * 16;

    int stage = 0;
    for (int i = 0; i < nchunk; i++) {
        if (i == nchunk - 1) asm volatile("cp.async.wait_group 0;" ::: "memory");
        else                 asm volatile("cp.async.wait_group 1;" ::: "memory");
        __syncthreads();

        const bool pf = (i + 2 < nchunk);
        int ns = stage + 2; if (ns >= 3) ns -= 3;
        const uint32_t pfSb = sm_base + (uint32_t)(ns * ST_B32) * 4;
        const __half* pfA = Ag + (size_t)(i + 2) * 64 + (size_t)r0 * K + u * 8;
        const __half* pfB = Bg + (size_t)(i + 2) * 64 + (size_t)r0 * K + u * 8;

        const uint32_t stBase = sm_base + (uint32_t)(stage * ST_B32) * 4;
        #pragma unroll
        for (int ks = 0; ks < 4; ks++) {
            const uint32_t kb = (uint32_t)ks * 32;
            uint32_t af[4][4], bf[4][2];
            #pragma unroll
            for (int mi = 0; mi < 4; mi++)
                ldsm_x4(af[mi][0], af[mi][1], af[mi][2], af[mi][3],
                        stBase + aOff + (uint32_t)mi * (16 * ROWB) + kb);
            #pragma unroll
            for (int np = 0; np < 2; np++)
                ldsm_x4(bf[2*np][0], bf[2*np][1], bf[2*np+1][0], bf[2*np+1][1],
                        stBase + bOff + (uint32_t)np * (16 * ROWB) + kb);
            if (pf) {
                cp16(pfSb + cpSmA0 + (uint32_t)ks * cpSmStep, pfA + (size_t)(ks * 32) * K);
                cp16(pfSb + cpSmB0 + (uint32_t)ks * cpSmStep, pfB + (size_t)(ks * 32) * K);
            }
            #pragma unroll
            for (int mi = 0; mi < 4; mi++)
                #pragma unroll
                for (int ni = 0; ni < 4; ni++)
                    asm volatile(
                        "mma.sync.aligned.m16n8k16.row.col.f32.f16.f16.f32 "
                        "{%0,%1,%2,%3}, {%4,%5,%6,%7}, {%8,%9}, {%0,%1,%2,%3};"
                        : "+f"(acc[mi][ni][0]), "+f"(acc[mi][ni][1]),
                          "+f"(acc[mi][ni][2]), "+f"(acc[mi][ni][3])
                        : "r"(af[mi][0]), "r"(af[mi][1]), "r"(af[mi][2]), "r"(af[mi][3]),
                          "r"(bf[ni][0]), "r"(bf[ni][1]));
        }
        if (pf) asm volatile("cp.async.commit_group;");
        if (++stage == 3) stage = 0;
    }

    // -------- epilogue --------
    float* Cf = (float*)Cv;
    __half* Ch = (__half*)Cv;
    const __half* sgh = (const __half*)aux1;
    #pragma unroll
    for (int mi = 0; mi < 4; mi++) {
        const int rbase = m0 + wm * 64 + mi * 16 + g;
        #pragma unroll
        for (int ni = 0; ni < 4; ni++) {
            const int cc = n0 + wn * 32 + ni * 8 + t * 2;
            #pragma unroll
            for (int half_ = 0; half_ < 2; half_++) {
                const int r = rbase + half_ * 8;
                float v0 = acc[mi][ni][half_ * 2 + 0];
                float v1 = acc[mi][ni][half_ * 2 + 1];
                const size_t off = (size_t)r * N + cc;
                if (EPI == EPI_NONE) {
                    float2 o = {v0, v1};
                    *(float2*)(Cf + off) = o;
                } else if (EPI == EPI_SIG) {
                    float2 gb = *(const float2*)(aux0 + cc);
                    __half2 o = __floats2half2_rn(sigmf(v0 + gb.x), sigmf(v1 + gb.y));
                    *(uint32_t*)(Ch + off) = h2u(o);
                } else if (EPI == EPI_GATE) {
                    uint32_t su = *(const uint32_t*)(sgh + off);
                    float2 sg = __half22float2(*(__half2*)&su);
                    float2 xr = *(const float2*)(aux2 + off);
                    float2 o = {xr.x + sg.x * v0, xr.y + sg.y * v1};
                    *(float2*)(Cf + off) = o;
                } else if (EPI == EPI_SILU_H) {
                    float2 bb = *(const float2*)(aux0 + cc);
                    float t0 = v0 + bb.x, t1 = v1 + bb.y;
                    __half2 o = __floats2half2_rn(t0 * sigmf(t0), t1 * sigmf(t1));
                    *(uint32_t*)(Ch + off) = h2u(o);
                } else if (EPI == EPI_BIAS_RES) {
                    float2 bb = *(const float2*)(aux0 + cc);
                    float2 xr = *(const float2*)(aux2 + off);
                    float2 o = {xr.x + v0 + bb.x, xr.y + v1 + bb.y};
                    *(float2*)(Cf + off) = o;
                }
            }
        }
    }
}

// ---------------- depthwise causal conv + bias + SiLU + mem inject ----------
__global__ void __launch_bounds__(256)
ten_conv_mem_kernel(const float* __restrict__ beta0,
                    const float* __restrict__ pm,
                    const float* __restrict__ conv_w,
                    const float* __restrict__ conv_b,
                    const float* __restrict__ mem_gate,
                    float* __restrict__ bR, float* __restrict__ bI)
{
    const int b   = blockIdx.z;
    const int cg0 = blockIdx.y * 32;
    const int t0  = blockIdx.x * 64;
    __shared__ float sb[67][33];
    __shared__ float sp[64][33];
    const int tid = threadIdx.x;

    for (int i = tid; i < 67 * 32; i += 256) {
        const int r = i >> 5, c = i & 31;
        const int t = t0 + r - 3;
        sb[r][c] = (t >= 0) ? beta0[((size_t)(b * TT + t)) * C2K + cg0 + c] : 0.f;
    }
    for (int i = tid; i < 64 * 32; i += 256) {
        const int r = i >> 5, c = i & 31;
        sp[r][c] = pm[((size_t)(b * TT + t0 + r)) * C2K + cg0 + c];
    }
    __syncthreads();

    const float mg = 1.f / (1.f + expf(-mem_gate[0]));
    const int cl = tid >> 3;
    const int tg = (tid & 7) * 8;
    const int cglob = cg0 + cl;
    const float w0 = conv_w[cglob * 4 + 0];
    const float w1 = conv_w[cglob * 4 + 1];
    const float w2 = conv_w[cglob * 4 + 2];
    const float w3 = conv_w[cglob * 4 + 3];
    const float cb = conv_b[cglob];
    const int k = cglob & (KK - 1);
    float* dst = ((cglob < KK) ? bR : bI) + ((size_t)(b * KK + k)) * TT + t0 + tg;
    #pragma unroll
    for (int j = 0; j < 8; j++) {
        const int r = tg + j;
        float v = sb[r][cl] * w0 + sb[r + 1][cl] * w1 + sb[r + 2][cl] * w2 + sb[r + 3][cl] * w3 + cb;
        v = v * (1.f / (1.f + __expf(-v)));
        v += mg * sp[r][cl];
        dst[j] = v;
    }
}

// ---------------- complex first-order recurrence scan -----------------------
__global__ void __launch_bounds__(256)
ten_scan_kernel(const float* __restrict__ bR, const float* __restrict__ bI,
                const float* __restrict__ log_decay, const float* __restrict__ freq,
                float* __restrict__ cR, float* __restrict__ cI)
{
    const int bk = blockIdx.x;
    const int k = bk & (KK - 1);
    const float mag = 1.f / (1.f + expf(-log_decay[k]));
    float snf, csf;
    sincosf(freq[k], &snf, &csf);
    const float lr = mag * csf, li = mag * snf;
    const int tid = threadIdx.x;
    const size_t base = (size_t)bk * TT + tid * 16;

    float xr[16], xi[16];
    #pragma unroll
    for (int v = 0; v < 4; v++) {
        float4 a = *(const float4*)(bR + base + v * 4);
        xr[v*4+0] = a.x; xr[v*4+1] = a.y; xr[v*4+2] = a.z; xr[v*4+3] = a.w;
        float4 c = *(const float4*)(bI + base + v * 4);
        xi[v*4+0] = c.x; xi[v*4+1] = c.y; xi[v*4+2] = c.z; xi[v*4+3] = c.w;
    }

    float cr = 0.f, ci = 0.f;
    #pragma unroll
    for (int j = 0; j < 16; j++) {
        float nr = fmaf(lr, cr, fmaf(-li, ci, xr[j]));
        float ni = fmaf(lr, ci, fmaf( li, cr, xi[j]));
        cr = nr; ci = ni;
        xr[j] = cr; xi[j] = ci;
    }

    float fr = lr, fi = li;
    #pragma unroll
    for (int s = 0; s < 4; s++) {
        float nr = fr * fr - fi * fi;
        float ni = 2.f * fr * fi;
        fr = nr; fi = ni;
    }

    __shared__ float sgr[256], sgi[256], sor[256], soi[256];
    sgr[tid] = fr; sgi[tid] = fi; sor[tid] = cr; soi[tid] = ci;
    __syncthreads();
    for (int d = 1; d < 256; d <<= 1) {
        float ngr = 0.f, ngi = 0.f, nor_ = 0.f, noi_ = 0.f;
        if (tid >= d) {
            const float pgr = sgr[tid - d], pgi = sgi[tid - d];
            const float por = sor[tid - d], poi = soi[tid - d];
            const float gr = sgr[tid], gi = sgi[tid];
            const float orr = sor[tid], oii = soi[tid];
            ngr  = gr * pgr - gi * pgi;
            ngi  = gr * pgi + gi * pgr;
            nor_ = gr * por - gi * poi + orr;
            noi_ = gr * poi + gi * por + oii;
        }
        __syncthreads();
        if (tid >= d) { sgr[tid] = ngr; sgi[tid] = ngi; sor[tid] = nor_; soi[tid] = noi_; }
        __syncthreads();
    }
    const float pr = (tid > 0) ? sor[tid - 1] : 0.f;
    const float pi = (tid > 0) ? soi[tid - 1] : 0.f;

    float lpr = lr, lpi = li;
    #pragma unroll
    for (int j = 0; j < 16; j++) {
        xr[j] = fmaf(lpr, pr, fmaf(-lpi, pi, xr[j]));
        xi[j] = fmaf(lpr, pi, fmaf( lpi, pr, xi[j]));
        float nr = lpr * lr - lpi * li;
        float ni = lpr * li + lpi * lr;
        lpr = nr; lpi = ni;
    }
    #pragma unroll
    for (int v = 0; v < 4; v++) {
        float4 a = {xr[v*4+0], xr[v*4+1], xr[v*4+2], xr[v*4+3]};
        *(float4*)(cR + base + v * 4) = a;
        float4 c = {xi[v*4+0], xi[v*4+1], xi[v*4+2], xi[v*4+3]};
        *(float4*)(cI + base + v * 4) = c;
    }
}

// ---------------- coupling + transpose -> eig fp32 (output) + fp16 copy -----
__global__ void __launch_bounds__(256)
ten_coupling_kernel(const float* __restrict__ cR, const float* __restrict__ cI,
                    const float* __restrict__ coupling,
                    float* __restrict__ eig, __half* __restrict__ eig_h)
{
    const int b = blockIdx.z, h = blockIdx.y;
    const int t0 = blockIdx.x * 256;
    const int tid = threadIdx.x;
    __shared__ float sr[16][256];
    __shared__ float si[16][256];
    __shared__ float w[16][16];
    w[tid >> 4][tid & 15] = coupling[h * 256 + tid];
    #pragma unroll
    for (int kk = 0; kk < 16; kk++) {
        const size_t src = ((size_t)(b * KK + h * 16 + kk)) * TT + t0 + tid;
        sr[kk][tid] = cR[src];
        si[kk][tid] = cI[src];
    }
    __syncthreads();
    float orr[16], oii[16];
    #pragma unroll
    for (int j = 0; j < 16; j++) { orr[j] = 0.f; oii[j] = 0.f; }
    #pragma unroll
    for (int kk = 0; kk < 16; kk++) {
        const float vr = sr[kk][tid];
        const float vi = si[kk][tid];
        #pragma unroll
        for (int j = 0; j < 16; j++) {
            orr[j] = fmaf(w[j][kk], vr, orr[j]);
            oii[j] = fmaf(w[j][kk], vi, oii[j]);
        }
    }
    const size_t dst = ((size_t)(b * TT + t0 + tid)) * C2K + h * 16;
    #pragma unroll
    for (int j = 0; j < 16; j += 4) {
        float4 v = {orr[j], orr[j+1], orr[j+2], orr[j+3]};
        *(float4*)(eig + dst + j) = v;
        float4 u = {oii[j], oii[j+1], oii[j+2], oii[j+3]};
        *(float4*)(eig + dst + KK + j) = u;
        uint2 vv = {h2u(__floats2half2_rn(orr[j], orr[j+1])),
                    h2u(__floats2half2_rn(orr[j+2], orr[j+3]))};
        *(uint2*)(eig_h + dst + j) = vv;
        uint2 uu = {h2u(__floats2half2_rn(oii[j], oii[j+1])),
                    h2u(__floats2half2_rn(oii[j+2], oii[j+3]))};
        *(uint2*)(eig_h + dst + KK + j) = uu;
    }
}

// ---------------- launch -----------------------------------------------------
extern "C" void kernel_launch(void* const* d_in, const int* in_sizes, int n_in,
                              void* d_out, int out_size)
{
    const float* x          = (const float*)d_in[0];
    const float* prev_eig   = (const float*)d_in[1];
    const float* in_proj_w  = (const float*)d_in[2];
    const float* conv_w     = (const float*)d_in[3];
    const float* conv_b     = (const float*)d_in[4];
    const float* mem_gate   = (const float*)d_in[5];
    const float* mem_proj_w = (const float*)d_in[6];
    const float* log_decay  = (const float*)d_in[7];
    const float* frequency  = (const float*)d_in[8];
    const float* coupling   = (const float*)d_in[9];
    const float* out_proj_w = (const float*)d_in[10];
    const float* gate_w     = (const float*)d_in[11];
    const float* gate_b     = (const float*)d_in[12];
    const float* mlp_w1     = (const float*)d_in[13];
    const float* mlp_b1     = (const float*)d_in[14];
    const float* mlp_w2     = (const float*)d_in[15];
    const float* mlp_b2     = (const float*)d_in[16];
    const float* n1_g       = (const float*)d_in[17];
    const float* n1_b       = (const float*)d_in[18];
    const float* n2_g       = (const float*)d_in[19];
    const float* n2_b       = (const float*)d_in[20];

    float* out_x2  = (float*)d_out;
    float* out_eig = out_x2 + (size_t)NT * DD;

    __half *xn_h, *y_h, *h1_h, *eig_h, *pe_h, *sig_h, *wh;
    float *beta0, *pm, *bRp, *bIp, *cRp, *cIp, *x1;
    cudaGetSymbolAddress((void**)&xn_h,  g_xn_h);
    cudaGetSymbolAddress((void**)&y_h,   g_y_h);
    cudaGetSymbolAddress((void**)&h1_h,  g_h1_h);
    cudaGetSymbolAddress((void**)&eig_h, g_eig_h);
    cudaGetSymbolAddress((void**)&pe_h,  g_pe_h);
    cudaGetSymbolAddress((void**)&sig_h, g_sig_h);
    cudaGetSymbolAddress((void**)&wh,    g_wh);
    cudaGetSymbolAddress((void**)&beta0, g_beta0);
    cudaGetSymbolAddress((void**)&pm,    g_pm);
    cudaGetSymbolAddress((void**)&bRp,   g_bR);
    cudaGetSymbolAddress((void**)&bIp,   g_bI);
    cudaGetSymbolAddress((void**)&cRp,   g_cR);
    cudaGetSymbolAddress((void**)&cIp,   g_cI);
    cudaGetSymbolAddress((void**)&x1,    g_x1);

    cudaFuncSetAttribute(mma_gemm<EPI_NONE>,     cudaFuncAttributeMaxDynamicSharedMemorySize, GEMM_SMEM);
    cudaFuncSetAttribute(mma_gemm<EPI_SIG>,      cudaFuncAttributeMaxDynamicSharedMemorySize, GEMM_SMEM);
    cudaFuncSetAttribute(mma_gemm<EPI_GATE>,     cudaFuncAttributeMaxDynamicSharedMemorySize, GEMM_SMEM);
    cudaFuncSetAttribute(mma_gemm<EPI_SILU_H>,   cudaFuncAttributeMaxDynamicSharedMemorySize, GEMM_SMEM);
    cudaFuncSetAttribute(mma_gemm<EPI_BIAS_RES>, cudaFuncAttributeMaxDynamicSharedMemorySize, GEMM_SMEM);

    // one-time stream/event handles (host objects only; identical launch
    // sequence every call, so determinism is preserved)
    static cudaStream_t s1 = nullptr;
    static cudaEvent_t evStart = nullptr, evCvt = nullptr, evLN1 = nullptr,
                       evPm = nullptr, evCoup = nullptr;
    if (s1 == nullptr) {
        cudaStreamCreateWithFlags(&s1, cudaStreamNonBlocking);
        cudaEventCreateWithFlags(&evStart, cudaEventDisableTiming);
        cudaEventCreateWithFlags(&evCvt,   cudaEventDisableTiming);
        cudaEventCreateWithFlags(&evLN1,   cudaEventDisableTiming);
        cudaEventCreateWithFlags(&evPm,    cudaEventDisableTiming);
        cudaEventCreateWithFlags(&evCoup,  cudaEventDisableTiming);
    }

    // fork s1 from the launch stream
    cudaEventRecord(evStart, 0);
    cudaStreamWaitEvent(s1, evStart, 0);

    // ---- s1 branch: LN1 (depends only on input x) ----
    ten_ln_kernel<<<NT, 256, 0, s1>>>(x, n1_g, n1_b, xn_h);
    cudaEventRecord(evLN1, s1);

    // ---- s0: weight conversion ----
    CvtArgs ca;
    ca.src[0] = in_proj_w;  ca.dst[0] = wh + W_INPROJ;  ca.n8[0] = (int)((size_t)C2K * DD / 8);
    ca.src[1] = mem_proj_w; ca.dst[1] = wh + W_MEMPROJ; ca.n8[1] = (int)((size_t)C2K * C2K / 8);
    ca.src[2] = out_proj_w; ca.dst[2] = wh + W_OUTPROJ; ca.n8[2] = (int)((size_t)DD * C2K / 8);
    ca.src[3] = gate_w;     ca.dst[3] = wh + W_GATE;    ca.n8[3] = (int)((size_t)DD * DD / 8);
    ca.src[4] = mlp_w1;     ca.dst[4] = wh + W_MLP1;    ca.n8[4] = (int)((size_t)MM * DD / 8);
    ca.src[5] = mlp_w2;     ca.dst[5] = wh + W_MLP2;    ca.n8[5] = (int)((size_t)DD * MM / 8);
    ca.src[6] = prev_eig;   ca.dst[6] = pe_h;           ca.n8[6] = (int)((size_t)NT * C2K / 8);
    cvt_all_kernel<<<dim3(2048, 7), 256>>>(ca);
    cudaEventRecord(evCvt, 0);

    // ---- s0: pm GEMM (needs cvt only) ----
    mma_gemm<EPI_NONE><<<dim3(C2K/128, NT/128), 256, GEMM_SMEM>>>(
        pe_h, wh + W_MEMPROJ, pm, NT, C2K, C2K, nullptr, nullptr, nullptr);
    cudaEventRecord(evPm, 0);

    // ---- s1 branch: in_proj (needs LN1 [s1-ordered] + cvt) ----
    cudaStreamWaitEvent(s1, evCvt, 0);
    mma_gemm<EPI_NONE><<<dim3(C2K/128, NT/128), 256, GEMM_SMEM, s1>>>(
        xn_h, wh + W_INPROJ, beta0, NT, C2K, DD, nullptr, nullptr, nullptr);

    // ---- s0: gate GEMM (needs cvt [s0-ordered] + LN1) ----
    cudaStreamWaitEvent(0, evLN1, 0);
    mma_gemm<EPI_SIG><<<dim3(DD/128, NT/128), 256, GEMM_SMEM>>>(
        xn_h, wh + W_GATE, sig_h, NT, DD, DD, gate_b, nullptr, nullptr);

    // ---- s1 branch: conv (needs beta0 [s1] + pm) -> scan -> coupling ----
    cudaStreamWaitEvent(s1, evPm, 0);
    ten_conv_mem_kernel<<<dim3(TT/64, C2K/32, BB), 256, 0, s1>>>(
        beta0, pm, conv_w, conv_b, mem_gate, bRp, bIp);
    ten_scan_kernel<<<BB * KK, 256, 0, s1>>>(bRp, bIp, log_decay, frequency, cRp, cIp);
    ten_coupling_kernel<<<dim3(TT/256, HH, BB), 256, 0, s1>>>(cRp, cIp, coupling, out_eig, eig_h);
    cudaEventRecord(evCoup, s1);

    // ---- join: out_proj needs coupling (s1) + gate (s0) ----
    cudaStreamWaitEvent(0, evCoup, 0);
    mma_gemm<EPI_GATE><<<dim3(DD/128, NT/128), 256, GEMM_SMEM>>>(
        eig_h, wh + W_OUTPROJ, x1, NT, DD, C2K, nullptr, sig_h, x);

    // ---- s0 tail: LN2, MLP ----
    ten_ln_kernel<<<NT, 256>>>(x1, n2_g, n2_b, y_h);
    mma_gemm<EPI_SILU_H><<<dim3(MM/128, NT/128), 256, GEMM_SMEM>>>(
        y_h, wh + W_MLP1, h1_h, NT, MM, DD, mlp_b1, nullptr, nullptr);
    mma_gemm<EPI_BIAS_RES><<<dim3(DD/128, NT/128), 256, GEMM_SMEM>>>(
        h1_h, wh + W_MLP2, out_x2, NT, DD, MM, mlp_b2, nullptr, x1);
}